// round 11
// baseline (speedup 1.0000x reference)
#include <cuda_runtime.h>
#include <cuda_bf16.h>
#include <math.h>
#include <stdint.h>

// Problem constants
constexpr int Bb = 4, Nn = 325, Tt = 48, Hh = 8;
constexpr int M  = Bb * Nn * Tt;      // 62400 tokens
constexpr int MT = 488;               // M tiles of 128
constexpr int M_PAD = MT * 128;       // 62464
constexpr float SCALE = 0.25f;        // HD^-0.5, HD=16
constexpr float EPS = 1e-5f;

// Scratch (device globals, zero-initialized; pad rows [M, M_PAD) never written)
__device__ float g_qkv[M_PAD * 384];
__device__ float g_x1 [M_PAD * 128];
__device__ float g_x2 [M_PAD * 128];
__device__ __nv_bfloat16 g_hh[M_PAD * 128], g_hl[M_PAD * 128];   // LN out hi/lo
__device__ __nv_bfloat16 g_ah[M_PAD * 128], g_al[M_PAD * 128];   // attn out hi/lo
__device__ __nv_bfloat16 g_fh[M_PAD * 512], g_fl[M_PAD * 512];   // ffn1 out hi/lo
__device__ __nv_bfloat16 g_wh[262144],      g_wl[262144];        // weights^T hi/lo

// Weight segment offsets in g_wh/g_wl ([N,K] layout each)
constexpr int W_TQKV = 0;        // 384x128
constexpr int W_TPRJ = 49152;    // 128x128
constexpr int W_SQKV = 65536;    // 384x128
constexpr int W_SPRJ = 114688;   // 128x128
constexpr int W_FW1  = 131072;   // 512x128
constexpr int W_FW2  = 196608;   // 128x512

// ---------------------------------------------------------------------------
// Baseline-PTX helpers (sm_80-class: mma.sync, ldmatrix, cp.async)
// ---------------------------------------------------------------------------
__device__ __forceinline__ uint32_t s2u(const void* p) {
    uint32_t a;
    asm("{ .reg .u64 t; cvta.to.shared.u64 t, %1; cvt.u32.u64 %0, t; }"
        : "=r"(a) : "l"(p));
    return a;
}

__device__ __forceinline__ void ldsm4(uint32_t& r0, uint32_t& r1,
                                      uint32_t& r2, uint32_t& r3, uint32_t a) {
    asm volatile("ldmatrix.sync.aligned.m8n8.x4.shared.b16 {%0,%1,%2,%3}, [%4];"
                 : "=r"(r0), "=r"(r1), "=r"(r2), "=r"(r3) : "r"(a));
}

__device__ __forceinline__ void mma_bf16(float* c, const uint32_t* a, const uint32_t* b) {
    asm volatile(
        "mma.sync.aligned.m16n8k16.row.col.f32.bf16.bf16.f32 "
        "{%0,%1,%2,%3}, {%4,%5,%6,%7}, {%8,%9}, {%0,%1,%2,%3};"
        : "+f"(c[0]), "+f"(c[1]), "+f"(c[2]), "+f"(c[3])
        : "r"(a[0]), "r"(a[1]), "r"(a[2]), "r"(a[3]), "r"(b[0]), "r"(b[1]));
}

__device__ __forceinline__ void cpasync16(uint32_t dst, const void* src) {
    asm volatile("cp.async.cg.shared.global [%0], [%1], 16;" :: "r"(dst), "l"(src));
}

// fp32 pair -> bf16 hi + bf16 lo (residual) packed as b32
__device__ __forceinline__ void split2(float x, float y, uint32_t& hi, uint32_t& lo) {
    __nv_bfloat162 h = __floats2bfloat162_rn(x, y);
    float rx = x - __bfloat162float(__low2bfloat16(h));
    float ry = y - __bfloat162float(__high2bfloat16(h));
    __nv_bfloat162 l = __floats2bfloat162_rn(rx, ry);
    hi = *(uint32_t*)&h;
    lo = *(uint32_t*)&l;
}

// A-row permutations for the spatial branch (token (b,n,t) <-> transposed (b,t,n))
// PERM 0: identity. PERM 1: m is in (b,t,n) order -> src token row (b,n,t).
// PERM 2: m is in (b,n,t) order -> src transposed row (b,t,n).
template <int PERM>
__device__ __forceinline__ int maprow(int m) {
    if (PERM == 0) return m;
    if (m >= M) return m;
    int b = m / 15600, r = m % 15600;
    if (PERM == 1) { int t = r / 325, n = r % 325; return (b * 325 + n) * 48 + t; }
    else           { int n = r / 48,  t = r % 48;  return (b * 48 + t) * 325 + n; }
}

// ---------------------------------------------------------------------------
// Fused weight transpose + split for all 6 weight matrices (one launch)
// ---------------------------------------------------------------------------
__global__ void wsplit_all(const float* __restrict__ w0, const float* __restrict__ w1,
                           const float* __restrict__ w2, const float* __restrict__ w3,
                           const float* __restrict__ w4, const float* __restrict__ w5,
                           __nv_bfloat16* __restrict__ hi, __nv_bfloat16* __restrict__ lo)
{
    int idx = blockIdx.x * 256 + threadIdx.x;
    if (idx >= 262144) return;
    const float* W; int K, N, local;
    if      (idx < 49152)  { W = w0; K = 128; N = 384; local = idx; }
    else if (idx < 65536)  { W = w1; K = 128; N = 128; local = idx - 49152; }
    else if (idx < 114688) { W = w2; K = 128; N = 384; local = idx - 65536; }
    else if (idx < 131072) { W = w3; K = 128; N = 128; local = idx - 114688; }
    else if (idx < 196608) { W = w4; K = 128; N = 512; local = idx - 131072; }
    else                   { W = w5; K = 512; N = 128; local = idx - 196608; }
    int n = local / K, k = local % K;
    float v = W[(size_t)k * N + n];
    __nv_bfloat16 h = __float2bfloat16(v);
    hi[idx] = h;
    lo[idx] = __float2bfloat16(v - __bfloat162float(h));
}

// ---------------------------------------------------------------------------
// LayerNorm: one warp per token row of 128 floats; outputs bf16 hi/lo
// ---------------------------------------------------------------------------
__global__ void ln_kernel(const float* __restrict__ X,
                          const float* __restrict__ s,
                          const float* __restrict__ b,
                          __nv_bfloat16* __restrict__ Ohi,
                          __nv_bfloat16* __restrict__ Olo, int rows)
{
    int gw   = (blockIdx.x * blockDim.x + threadIdx.x) >> 5;
    int lane = threadIdx.x & 31;
    if (gw >= rows) return;
    float4 v = ((const float4*)(X + (size_t)gw * 128))[lane];
    float sum = v.x + v.y + v.z + v.w;
    #pragma unroll
    for (int o = 16; o; o >>= 1) sum += __shfl_xor_sync(0xffffffffu, sum, o);
    float mean = sum * (1.0f / 128.0f);
    float dx = (v.x - mean) * (v.x - mean) + (v.y - mean) * (v.y - mean)
             + (v.z - mean) * (v.z - mean) + (v.w - mean) * (v.w - mean);
    #pragma unroll
    for (int o = 16; o; o >>= 1) dx += __shfl_xor_sync(0xffffffffu, dx, o);
    float rstd = rsqrtf(dx * (1.0f / 128.0f) + EPS);
    float4 sv = ((const float4*)s)[lane];
    float4 bv = ((const float4*)b)[lane];
    float o0 = (v.x - mean) * rstd * sv.x + bv.x;
    float o1 = (v.y - mean) * rstd * sv.y + bv.y;
    float o2 = (v.z - mean) * rstd * sv.z + bv.z;
    float o3 = (v.w - mean) * rstd * sv.w + bv.w;
    uint32_t h0, l0, h1, l1;
    split2(o0, o1, h0, l0);
    split2(o2, o3, h1, l1);
    uint2 hv; hv.x = h0; hv.y = h1;
    uint2 lv; lv.x = l0; lv.y = l1;
    ((uint2*)(Ohi + (size_t)gw * 128))[lane] = hv;
    ((uint2*)(Olo + (size_t)gw * 128))[lane] = lv;
}

// ---------------------------------------------------------------------------
// Pre-split bf16 tensor-core GEMM: C = Ahi/lo @ (Bhi/lo)^T + bias (+res)(gelu)
// CTA 128x128, BK=32, 256 threads (8 warps 4Mx2N, warp tile 32x64).
// Double-buffered cp.async. D = Ahi*Bhi + Ahi*Blo + Alo*Bhi (fp32 accum).
// EPI: 0 = bias->fp32 C; 1 = bias+res->fp32 C; 2 = bias+GELU->bf16 hi/lo C
// PERM: A-row permutation (see maprow).
// ---------------------------------------------------------------------------
constexpr int ST = 40;                 // smem row stride in bf16 (80B)
constexpr int BUF = 128 * ST * 2;      // 10240 B per operand buffer
constexpr int STAGE = 4 * BUF;         // 40960 B per stage
constexpr int GSMEM = 2 * STAGE;       // 81920 B total

template <int EPI, int PERM = 0>
__global__ __launch_bounds__(256)
void gemm_bf(const __nv_bfloat16* __restrict__ Ahi, const __nv_bfloat16* __restrict__ Alo,
             const __nv_bfloat16* __restrict__ Bhi, const __nv_bfloat16* __restrict__ Blo,
             const float* __restrict__ bias, const float* __restrict__ Res,
             float* __restrict__ C,
             __nv_bfloat16* __restrict__ Chi, __nv_bfloat16* __restrict__ Clo,
             int Nc, int K, int Mreal)
{
    extern __shared__ char smem[];
    const int tid  = threadIdx.x;
    const int lane = tid & 31;
    const int wid  = tid >> 5;
    const int wm   = wid & 3;
    const int wn   = wid >> 2;
    const int m0   = blockIdx.y * 128;
    const int gn0  = blockIdx.x * 128;
    const uint32_t sbase = s2u(smem);

    float acc[2][8][4] = {};
    const int nch = K / 32;

    const int asub = lane >> 3;
    const int arow = (lane & 7) + (asub & 1) * 8;
    const int acol = (asub >> 1) * 8;
    const int bnof = (lane & 7) + ((lane >> 3) >> 1) * 8;
    const int bkof = ((lane >> 3) & 1) * 8;

    // A source rows for this thread's two load slots (permuted once)
    int asrc0 = maprow<PERM>(m0 + (tid >> 2));
    int asrc1 = maprow<PERM>(m0 + ((256 + tid) >> 2));

    auto issue = [&](int c) {
        const int k0 = c * 32;
        const uint32_t st = sbase + (c & 1) * STAGE;
        #pragma unroll
        for (int i = 0; i < 2; i++) {
            int u = i * 256 + tid, row = u >> 2, g = u & 3;
            int srow = i ? asrc1 : asrc0;
            size_t go = (size_t)srow * K + k0 + g * 8;
            uint32_t dst = st + row * 80 + g * 16;
            cpasync16(dst,       Ahi + go);
            cpasync16(dst + BUF, Alo + go);
        }
        #pragma unroll
        for (int i = 0; i < 2; i++) {
            int u = i * 256 + tid, n = u >> 2, g = u & 3;
            size_t go = (size_t)(gn0 + n) * K + k0 + g * 8;
            uint32_t dst = st + 2 * BUF + n * 80 + g * 16;
            cpasync16(dst,       Bhi + go);
            cpasync16(dst + BUF, Blo + go);
        }
        asm volatile("cp.async.commit_group;");
    };

    issue(0);
    for (int c = 0; c < nch; c++) {
        if (c + 1 < nch) {
            issue(c + 1);
            asm volatile("cp.async.wait_group 1;");
        } else {
            asm volatile("cp.async.wait_group 0;");
        }
        __syncthreads();

        const uint32_t aH = sbase + (c & 1) * STAGE;
        const uint32_t aL = aH + BUF;
        const uint32_t bH = aH + 2 * BUF;
        const uint32_t bL = aH + 3 * BUF;

        #pragma unroll
        for (int ks = 0; ks < 2; ks++) {
            uint32_t ah[2][4], al[2][4], bh[8][2], bl[8][2];
            #pragma unroll
            for (int mt = 0; mt < 2; mt++) {
                uint32_t off = (uint32_t)((wm * 32 + mt * 16 + arow) * ST + ks * 16 + acol) * 2;
                ldsm4(ah[mt][0], ah[mt][1], ah[mt][2], ah[mt][3], aH + off);
                ldsm4(al[mt][0], al[mt][1], al[mt][2], al[mt][3], aL + off);
            }
            #pragma unroll
            for (int np = 0; np < 4; np++) {
                uint32_t off = (uint32_t)((wn * 64 + np * 16 + bnof) * ST + ks * 16 + bkof) * 2;
                ldsm4(bh[2*np][0], bh[2*np][1], bh[2*np+1][0], bh[2*np+1][1], bH + off);
                ldsm4(bl[2*np][0], bl[2*np][1], bl[2*np+1][0], bl[2*np+1][1], bL + off);
            }
            #pragma unroll
            for (int mt = 0; mt < 2; mt++)
                #pragma unroll
                for (int nt = 0; nt < 8; nt++) {
                    mma_bf16(acc[mt][nt], ah[mt], bh[nt]);
                    mma_bf16(acc[mt][nt], ah[mt], bl[nt]);
                    mma_bf16(acc[mt][nt], al[mt], bh[nt]);
                }
        }
        __syncthreads();
    }

    const int r0 = m0 + wm * 32 + (lane >> 2);
    const int c0 = gn0 + wn * 64 + (lane & 3) * 2;
    #pragma unroll
    for (int mt = 0; mt < 2; mt++) {
        #pragma unroll
        for (int half = 0; half < 2; half++) {
            int r = r0 + mt * 16 + half * 8;
            if (r < Mreal) {
                #pragma unroll
                for (int nt = 0; nt < 8; nt++) {
                    int cc = c0 + nt * 8;
                    float v0 = acc[mt][nt][half * 2 + 0] + bias[cc];
                    float v1 = acc[mt][nt][half * 2 + 1] + bias[cc + 1];
                    if (EPI == 1) {
                        float2 rv = *(const float2*)(Res + (size_t)r * Nc + cc);
                        v0 += rv.x; v1 += rv.y;
                    }
                    if (EPI == 2) {
                        v0 = 0.5f * v0 * (1.0f + erff(v0 * 0.70710678118654752f));
                        v1 = 0.5f * v1 * (1.0f + erff(v1 * 0.70710678118654752f));
                        uint32_t h, l;
                        split2(v0, v1, h, l);
                        *(uint32_t*)(Chi + (size_t)r * Nc + cc) = h;
                        *(uint32_t*)(Clo + (size_t)r * Nc + cc) = l;
                    } else {
                        float2 o; o.x = v0; o.y = v1;
                        *(float2*)(C + (size_t)r * Nc + cc) = o;
                    }
                }
            }
        }
    }
}

// ---------------------------------------------------------------------------
// Temporal attention v2: block per (b,n,head), L=48, HD=16; bf16 hi/lo out.
// ---------------------------------------------------------------------------
__global__ __launch_bounds__(64, 8)
void attn_temporal(const float* __restrict__ qkv,
                   __nv_bfloat16* __restrict__ Ohi, __nv_bfloat16* __restrict__ Olo)
{
    int h  = blockIdx.x & 7;
    int bn = blockIdx.x >> 3;
    __shared__ float q[48][20], k[48][20], v[48][20];
    __shared__ float sc[48][50];
    int tid = threadIdx.x;

    size_t base = (size_t)bn * 48 * 384 + h * 16;
    #pragma unroll 1
    for (int i = tid; i < 48 * 4; i += 64) {
        int row = i >> 2, seg = i & 3;
        const float* p = qkv + base + (size_t)row * 384;
        *(float4*)&q[row][seg * 4] = ((const float4*)(p))[seg];
        *(float4*)&k[row][seg * 4] = ((const float4*)(p + 128))[seg];
        *(float4*)&v[row][seg * 4] = ((const float4*)(p + 256))[seg];
    }
    __syncthreads();

    #pragma unroll 1
    for (int i = tid; i < 48 * 48; i += 64) {
        int qi = i / 48, ki = i % 48;
        float4 a0 = *(const float4*)&q[qi][0],  a1 = *(const float4*)&q[qi][4];
        float4 a2 = *(const float4*)&q[qi][8],  a3 = *(const float4*)&q[qi][12];
        float4 b0 = *(const float4*)&k[ki][0],  b1 = *(const float4*)&k[ki][4];
        float4 b2 = *(const float4*)&k[ki][8],  b3 = *(const float4*)&k[ki][12];
        float s = a0.x*b0.x + a0.y*b0.y + a0.z*b0.z + a0.w*b0.w
                + a1.x*b1.x + a1.y*b1.y + a1.z*b1.z + a1.w*b1.w
                + a2.x*b2.x + a2.y*b2.y + a2.z*b2.z + a2.w*b2.w
                + a3.x*b3.x + a3.y*b3.y + a3.z*b3.z + a3.w*b3.w;
        sc[qi][ki] = s * SCALE;
    }
    __syncthreads();

    if (tid < 48) {
        float mx = -3.4e38f;
        #pragma unroll 1
        for (int j = 0; j < 48; j++) mx = fmaxf(mx, sc[tid][j]);
        float l = 0.f;
        #pragma unroll 1
        for (int j = 0; j < 48; j++) {
            float p = __expf(sc[tid][j] - mx);
            sc[tid][j] = p; l += p;
        }
        float inv = 1.0f / l;
        #pragma unroll 1
        for (int j = 0; j < 48; j++) sc[tid][j] *= inv;
    }
    __syncthreads();

    #pragma unroll 1
    for (int i = tid; i < 48 * 4; i += 64) {
        int qi = i >> 2, seg = i & 3;
        float4 o = make_float4(0.f, 0.f, 0.f, 0.f);
        #pragma unroll 8
        for (int kk = 0; kk < 48; kk++) {
            float w = sc[qi][kk];
            float4 vv = *(const float4*)&v[kk][seg * 4];
            o.x = fmaf(w, vv.x, o.x);
            o.y = fmaf(w, vv.y, o.y);
            o.z = fmaf(w, vv.z, o.z);
            o.w = fmaf(w, vv.w, o.w);
        }
        uint32_t h0, l0, h1, l1;
        split2(o.x, o.y, h0, l0);
        split2(o.z, o.w, h1, l1);
        size_t off = (size_t)(bn * 48 + qi) * 128 + h * 16 + seg * 4;
        uint2 hv; hv.x = h0; hv.y = h1;
        uint2 lv; lv.x = l0; lv.y = l1;
        *(uint2*)(Ohi + off) = hv;
        *(uint2*)(Olo + off) = lv;
    }
}

// ---------------------------------------------------------------------------
// Spatial attention via mma.sync on TRANSPOSED qkv (rows in (b,t,n) order,
// key stride 1536B -> L2-resident tiles). Math identical to verified R9.
// Block = (qtile 128, head, b*t lin); 4 warps; warp owns 32 q-rows.
// Output written in transposed (b,t,n) row order (proj GEMM un-permutes).
// ---------------------------------------------------------------------------
__global__ __launch_bounds__(128)
void attn_spatial_mma(const float* __restrict__ qkvT, const int* __restrict__ mask,
                      __nv_bfloat16* __restrict__ Ohi, __nv_bfloat16* __restrict__ Olo)
{
    __shared__ __nv_bfloat16 sQh[128 * 16], sQl[128 * 16];
    __shared__ __nv_bfloat16 sKh[64 * 16],  sKl[64 * 16];
    __shared__ __nv_bfloat16 sVh[16 * 64],  sVl[16 * 64];
    __shared__ float mbias[384];

    const int tid = threadIdx.x, lane = tid & 31, warp = tid >> 5;
    const int qt = blockIdx.x, h = blockIdx.y, z = blockIdx.z;  // z = b*48+t
    const int b = z / Tt;
    const int q0 = qt * 128;
    const size_t rowbase = (size_t)z * Nn;   // row index base in transposed layout

    for (int j = tid; j < 384; j += 128)
        mbias[j] = (j < Nn && mask[b * Nn + j] != 0) ? 0.f : -1e30f;

    // Q tile load + split (rows >= Nn zeroed)
    for (int i = tid; i < 512; i += 128) {
        int row = i >> 2, seg = i & 3;
        int n = q0 + row;
        float4 v = make_float4(0.f, 0.f, 0.f, 0.f);
        if (n < Nn)
            v = *(const float4*)(qkvT + (rowbase + n) * 384 + h * 16 + seg * 4);
        uint32_t h0, l0, h1, l1;
        split2(v.x, v.y, h0, l0);
        split2(v.z, v.w, h1, l1);
        *(uint32_t*)&sQh[row * 16 + seg * 4]     = h0;
        *(uint32_t*)&sQh[row * 16 + seg * 4 + 2] = h1;
        *(uint32_t*)&sQl[row * 16 + seg * 4]     = l0;
        *(uint32_t*)&sQl[row * 16 + seg * 4 + 2] = l1;
    }
    __syncthreads();

    const int asub = lane >> 3;
    const int arow = (lane & 7) + (asub & 1) * 8;
    const int acol = (asub >> 1) * 8;
    const int bnof = (lane & 7) + ((lane >> 3) >> 1) * 8;
    const int bkof = ((lane >> 3) & 1) * 8;

    uint32_t qh[2][4], ql[2][4];
    const uint32_t qhB = s2u(sQh), qlB = s2u(sQl);
    #pragma unroll
    for (int mt = 0; mt < 2; mt++) {
        uint32_t off = (uint32_t)((warp * 32 + mt * 16 + arow) * 16 + acol) * 2;
        ldsm4(qh[mt][0], qh[mt][1], qh[mt][2], qh[mt][3], qhB + off);
        ldsm4(ql[mt][0], ql[mt][1], ql[mt][2], ql[mt][3], qlB + off);
    }

    const uint32_t khB = s2u(sKh), klB = s2u(sKl);
    const uint32_t vhB = s2u(sVh), vlB = s2u(sVl);

    float mrow[2][2], lrow[2][2], acc[2][2][4];
    #pragma unroll
    for (int mt = 0; mt < 2; mt++)
        #pragma unroll
        for (int hf = 0; hf < 2; hf++) {
            mrow[mt][hf] = -1e30f; lrow[mt][hf] = 0.f;
            acc[mt][0][hf*2] = acc[mt][0][hf*2+1] = 0.f;
            acc[mt][1][hf*2] = acc[mt][1][hf*2+1] = 0.f;
        }

    for (int kt = 0; kt < 6; kt++) {
        __syncthreads();
        // K/V tile load: exactly 128 work items = 64 keys x 2 segments
        {
            int i = tid;
            int key = i >> 1, seg = (i & 1) * 2;     // seg in {0,2}
            int n = kt * 64 + key;
            const float* base = qkvT + (rowbase + (n < Nn ? n : 0)) * 384 + h * 16;
            float4 kv0 = make_float4(0,0,0,0), kv1 = make_float4(0,0,0,0);
            float4 vv0 = make_float4(0,0,0,0), vv1 = make_float4(0,0,0,0);
            if (n < Nn) {
                kv0 = ((const float4*)(base + 128))[seg];
                kv1 = ((const float4*)(base + 128))[seg + 1];
                vv0 = ((const float4*)(base + 256))[seg];
                vv1 = ((const float4*)(base + 256))[seg + 1];
            }
            uint32_t h0, l0, h1, l1;
            split2(kv0.x, kv0.y, h0, l0); split2(kv0.z, kv0.w, h1, l1);
            *(uint32_t*)&sKh[key * 16 + seg * 4]     = h0;
            *(uint32_t*)&sKh[key * 16 + seg * 4 + 2] = h1;
            *(uint32_t*)&sKl[key * 16 + seg * 4]     = l0;
            *(uint32_t*)&sKl[key * 16 + seg * 4 + 2] = l1;
            split2(kv1.x, kv1.y, h0, l0); split2(kv1.z, kv1.w, h1, l1);
            *(uint32_t*)&sKh[key * 16 + seg * 4 + 4] = h0;
            *(uint32_t*)&sKh[key * 16 + seg * 4 + 6] = h1;
            *(uint32_t*)&sKl[key * 16 + seg * 4 + 4] = l0;
            *(uint32_t*)&sKl[key * 16 + seg * 4 + 6] = l1;
            float vf[8] = {vv0.x, vv0.y, vv0.z, vv0.w, vv1.x, vv1.y, vv1.z, vv1.w};
            #pragma unroll
            for (int d = 0; d < 8; d++) {
                float x = vf[d];
                __nv_bfloat16 hb = __float2bfloat16(x);
                sVh[(seg * 4 + d) * 64 + key] = hb;
                sVl[(seg * 4 + d) * 64 + key] = __float2bfloat16(x - __bfloat162float(hb));
            }
        }
        __syncthreads();

        #pragma unroll
        for (int mt = 0; mt < 2; mt++) {
            float sc[8][4];
            #pragma unroll
            for (int nt = 0; nt < 8; nt++) { sc[nt][0]=sc[nt][1]=sc[nt][2]=sc[nt][3]=0.f; }
            #pragma unroll
            for (int np = 0; np < 4; np++) {
                uint32_t off = (uint32_t)((np * 16 + bnof) * 16 + bkof) * 2;
                uint32_t kh[2][2], kl[2][2];
                ldsm4(kh[0][0], kh[0][1], kh[1][0], kh[1][1], khB + off);
                ldsm4(kl[0][0], kl[0][1], kl[1][0], kl[1][1], klB + off);
                #pragma unroll
                for (int half = 0; half < 2; half++) {
                    int nt = np * 2 + half;
                    mma_bf16(sc[nt], qh[mt], kh[half]);
                    mma_bf16(sc[nt], qh[mt], kl[half]);
                    mma_bf16(sc[nt], ql[mt], kh[half]);
                }
            }
            #pragma unroll
            for (int nt = 0; nt < 8; nt++) {
                float2 mb = *(float2*)&mbias[kt * 64 + nt * 8 + (lane & 3) * 2];
                sc[nt][0] = sc[nt][0] * SCALE + mb.x;
                sc[nt][1] = sc[nt][1] * SCALE + mb.y;
                sc[nt][2] = sc[nt][2] * SCALE + mb.x;
                sc[nt][3] = sc[nt][3] * SCALE + mb.y;
            }
            float mx0 = -1e30f, mx1 = -1e30f;
            #pragma unroll
            for (int nt = 0; nt < 8; nt++) {
                mx0 = fmaxf(mx0, fmaxf(sc[nt][0], sc[nt][1]));
                mx1 = fmaxf(mx1, fmaxf(sc[nt][2], sc[nt][3]));
            }
            #pragma unroll
            for (int o = 1; o <= 2; o <<= 1) {
                mx0 = fmaxf(mx0, __shfl_xor_sync(0xffffffffu, mx0, o));
                mx1 = fmaxf(mx1, __shfl_xor_sync(0xffffffffu, mx1, o));
            }
            float mn0 = fmaxf(mrow[mt][0], mx0);
            float mn1 = fmaxf(mrow[mt][1], mx1);
            float cor0 = __expf(mrow[mt][0] - mn0);
            float cor1 = __expf(mrow[mt][1] - mn1);
            mrow[mt][0] = mn0; mrow[mt][1] = mn1;
            float ls0 = 0.f, ls1 = 0.f;
            uint32_t aph[4][4], apl[4][4];
            #pragma unroll
            for (int kk = 0; kk < 4; kk++) {
                #pragma unroll
                for (int half = 0; half < 2; half++) {
                    int nt = kk * 2 + half;
                    float p0 = (sc[nt][0] > -1e29f) ? __expf(sc[nt][0] - mn0) : 0.f;
                    float p1 = (sc[nt][1] > -1e29f) ? __expf(sc[nt][1] - mn0) : 0.f;
                    float p2 = (sc[nt][2] > -1e29f) ? __expf(sc[nt][2] - mn1) : 0.f;
                    float p3 = (sc[nt][3] > -1e29f) ? __expf(sc[nt][3] - mn1) : 0.f;
                    ls0 += p0 + p1; ls1 += p2 + p3;
                    uint32_t h01, l01, h23, l23;
                    split2(p0, p1, h01, l01);
                    split2(p2, p3, h23, l23);
                    aph[kk][half * 2 + 0] = h01;
                    aph[kk][half * 2 + 1] = h23;
                    apl[kk][half * 2 + 0] = l01;
                    apl[kk][half * 2 + 1] = l23;
                }
            }
            lrow[mt][0] = lrow[mt][0] * cor0 + ls0;
            lrow[mt][1] = lrow[mt][1] * cor1 + ls1;
            #pragma unroll
            for (int nv = 0; nv < 2; nv++) {
                acc[mt][nv][0] *= cor0; acc[mt][nv][1] *= cor0;
                acc[mt][nv][2] *= cor1; acc[mt][nv][3] *= cor1;
            }
            #pragma unroll
            for (int kk = 0; kk < 4; kk++) {
                uint32_t off = (uint32_t)(bnof * 64 + kk * 16 + bkof) * 2;
                uint32_t vh[2][2], vl[2][2];
                ldsm4(vh[0][0], vh[0][1], vh[1][0], vh[1][1], vhB + off);
                ldsm4(vl[0][0], vl[0][1], vl[1][0], vl[1][1], vlB + off);
                #pragma unroll
                for (int nv = 0; nv < 2; nv++) {
                    mma_bf16(acc[mt][nv], aph[kk], vh[nv]);
                    mma_bf16(acc[mt][nv], aph[kk], vl[nv]);
                    mma_bf16(acc[mt][nv], apl[kk], vh[nv]);
                }
            }
        }
    }

    #pragma unroll
    for (int mt = 0; mt < 2; mt++) {
        float l0 = lrow[mt][0], l1 = lrow[mt][1];
        #pragma unroll
        for (int o = 1; o <= 2; o <<= 1) {
            l0 += __shfl_xor_sync(0xffffffffu, l0, o);
            l1 += __shfl_xor_sync(0xffffffffu, l1, o);
        }
        float inv0 = 1.0f / l0, inv1 = 1.0f / l1;
        #pragma unroll
        for (int hf = 0; hf < 2; hf++) {
            int row = q0 + warp * 32 + mt * 16 + (lane >> 2) + hf * 8;
            if (row < Nn) {
                float inv = hf ? inv1 : inv0;
                size_t tok = rowbase + row;          // transposed row order
                #pragma unroll
                for (int nv = 0; nv < 2; nv++) {
                    int d = nv * 8 + (lane & 3) * 2;
                    float o0 = acc[mt][nv][hf * 2 + 0] * inv;
                    float o1 = acc[mt][nv][hf * 2 + 1] * inv;
                    uint32_t hh, ll;
                    split2(o0, o1, hh, ll);
                    *(uint32_t*)&Ohi[tok * 128 + h * 16 + d] = hh;
                    *(uint32_t*)&Olo[tok * 128 + h * 16 + d] = ll;
                }
            }
        }
    }
}

// ---------------------------------------------------------------------------
// Orchestration
// ---------------------------------------------------------------------------
extern "C" void kernel_launch(void* const* d_in, const int* in_sizes, int n_in,
                              void* d_out, int out_size)
{
    const float* x       = (const float*)d_in[0];
    const int*   mask    = (const int*)  d_in[1];
    const float* ln1_s   = (const float*)d_in[2];
    const float* ln1_b   = (const float*)d_in[3];
    const float* tqkv_w  = (const float*)d_in[4];
    const float* tqkv_b  = (const float*)d_in[5];
    const float* tproj_w = (const float*)d_in[6];
    const float* tproj_b = (const float*)d_in[7];
    const float* ln2_s   = (const float*)d_in[8];
    const float* ln2_b   = (const float*)d_in[9];
    const float* sqkv_w  = (const float*)d_in[10];
    const float* sqkv_b  = (const float*)d_in[11];
    const float* sproj_w = (const float*)d_in[12];
    const float* sproj_b = (const float*)d_in[13];
    const float* ln3_s   = (const float*)d_in[14];
    const float* ln3_b   = (const float*)d_in[15];
    const float* fw1     = (const float*)d_in[16];
    const float* fb1     = (const float*)d_in[17];
    const float* fw2     = (const float*)d_in[18];
    const float* fb2     = (const float*)d_in[19];
    float* out = (float*)d_out;

    float *qkv, *x1, *x2;
    __nv_bfloat16 *hh, *hl, *ah, *al, *fh, *fl, *wh, *wl;
    cudaGetSymbolAddress((void**)&qkv, g_qkv);
    cudaGetSymbolAddress((void**)&x1,  g_x1);
    cudaGetSymbolAddress((void**)&x2,  g_x2);
    cudaGetSymbolAddress((void**)&hh,  g_hh);
    cudaGetSymbolAddress((void**)&hl,  g_hl);
    cudaGetSymbolAddress((void**)&ah,  g_ah);
    cudaGetSymbolAddress((void**)&al,  g_al);
    cudaGetSymbolAddress((void**)&fh,  g_fh);
    cudaGetSymbolAddress((void**)&fl,  g_fl);
    cudaGetSymbolAddress((void**)&wh,  g_wh);
    cudaGetSymbolAddress((void**)&wl,  g_wl);

    cudaFuncSetAttribute(gemm_bf<0>, cudaFuncAttributeMaxDynamicSharedMemorySize, GSMEM);
    cudaFuncSetAttribute(gemm_bf<1>, cudaFuncAttributeMaxDynamicSharedMemorySize, GSMEM);
    cudaFuncSetAttribute(gemm_bf<2>, cudaFuncAttributeMaxDynamicSharedMemorySize, GSMEM);
    cudaFuncSetAttribute((const void*)gemm_bf<0,1>, cudaFuncAttributeMaxDynamicSharedMemorySize, GSMEM);
    cudaFuncSetAttribute((const void*)gemm_bf<1,2>, cudaFuncAttributeMaxDynamicSharedMemorySize, GSMEM);

    // one-time weight transpose + split (single launch)
    wsplit_all<<<1024, 256>>>(tqkv_w, tproj_w, sqkv_w, sproj_w, fw1, fw2, wh, wl);

    const int ln_grid = (M + 7) / 8;
    dim3 g_qkv_grid(3, MT);    // N=384
    dim3 g_d_grid  (1, MT);    // N=128
    dim3 g_ffn1    (4, MT);    // N=512
    dim3 g_spat    (3, Hh, Bb * Tt);

    // ---- temporal branch ----
    ln_kernel<<<ln_grid, 256>>>(x, ln1_s, ln1_b, hh, hl, M);
    gemm_bf<0><<<g_qkv_grid, 256, GSMEM>>>(hh, hl, wh + W_TQKV, wl + W_TQKV,
                                           tqkv_b, nullptr, qkv, nullptr, nullptr, 384, 128, M);
    attn_temporal<<<Bb * Nn * Hh, 64>>>(qkv, ah, al);
    gemm_bf<1><<<g_d_grid, 256, GSMEM>>>(ah, al, wh + W_TPRJ, wl + W_TPRJ,
                                         tproj_b, x, x1, nullptr, nullptr, 128, 128, M);

    // ---- spatial branch (qkv produced in transposed (b,t,n) row order) ----
    ln_kernel<<<ln_grid, 256>>>(x1, ln2_s, ln2_b, hh, hl, M);
    gemm_bf<0,1><<<g_qkv_grid, 256, GSMEM>>>(hh, hl, wh + W_SQKV, wl + W_SQKV,
                                             sqkv_b, nullptr, qkv, nullptr, nullptr, 384, 128, M);
    attn_spatial_mma<<<g_spat, 128>>>(qkv, mask, ah, al);
    gemm_bf<1,2><<<g_d_grid, 256, GSMEM>>>(ah, al, wh + W_SPRJ, wl + W_SPRJ,
                                           sproj_b, x1, x2, nullptr, nullptr, 128, 128, M);

    // ---- FFN ----
    ln_kernel<<<ln_grid, 256>>>(x2, ln3_s, ln3_b, hh, hl, M);
    gemm_bf<2><<<g_ffn1, 256, GSMEM>>>(hh, hl, wh + W_FW1, wl + W_FW1,
                                       fb1, nullptr, nullptr, fh, fl, 512, 128, M);
    gemm_bf<1><<<g_d_grid, 256, GSMEM>>>(fh, fl, wh + W_FW2, wl + W_FW2,
                                         fb2, x2, out, nullptr, nullptr, 128, 512, M);
}

// round 12
// speedup vs baseline: 1.4126x; 1.4126x over previous
#include <cuda_runtime.h>
#include <cuda_bf16.h>
#include <math.h>
#include <stdint.h>

// Problem constants
constexpr int Bb = 4, Nn = 325, Tt = 48, Hh = 8;
constexpr int M  = Bb * Nn * Tt;      // 62400 tokens
constexpr int MT = 488;               // M tiles of 128
constexpr int M_PAD = MT * 128;       // 62464
constexpr float SCALE = 0.25f;        // HD^-0.5, HD=16
constexpr float EPS = 1e-5f;

// Scratch (device globals, zero-initialized; pad rows [M, M_PAD) never written)
__device__ float g_qkv[M_PAD * 384];
__device__ float g_x1 [M_PAD * 128];
__device__ float g_x2 [M_PAD * 128];
__device__ __nv_bfloat16 g_hh[M_PAD * 128], g_hl[M_PAD * 128];   // LN out hi/lo
__device__ __nv_bfloat16 g_ah[M_PAD * 128], g_al[M_PAD * 128];   // attn out hi/lo
__device__ __nv_bfloat16 g_fh[M_PAD * 512], g_fl[M_PAD * 512];   // ffn1 out hi/lo
__device__ __nv_bfloat16 g_wh[262144],      g_wl[262144];        // weights^T hi/lo

// Weight segment offsets in g_wh/g_wl ([N,K] layout each)
constexpr int W_TQKV = 0;        // 384x128
constexpr int W_TPRJ = 49152;    // 128x128
constexpr int W_SQKV = 65536;    // 384x128
constexpr int W_SPRJ = 114688;   // 128x128
constexpr int W_FW1  = 131072;   // 512x128
constexpr int W_FW2  = 196608;   // 128x512

// ---------------------------------------------------------------------------
// Baseline-PTX helpers (sm_80-class: mma.sync, ldmatrix, cp.async)
// ---------------------------------------------------------------------------
__device__ __forceinline__ uint32_t s2u(const void* p) {
    uint32_t a;
    asm("{ .reg .u64 t; cvta.to.shared.u64 t, %1; cvt.u32.u64 %0, t; }"
        : "=r"(a) : "l"(p));
    return a;
}

__device__ __forceinline__ void ldsm4(uint32_t& r0, uint32_t& r1,
                                      uint32_t& r2, uint32_t& r3, uint32_t a) {
    asm volatile("ldmatrix.sync.aligned.m8n8.x4.shared.b16 {%0,%1,%2,%3}, [%4];"
                 : "=r"(r0), "=r"(r1), "=r"(r2), "=r"(r3) : "r"(a));
}

__device__ __forceinline__ void mma_bf16(float* c, const uint32_t* a, const uint32_t* b) {
    asm volatile(
        "mma.sync.aligned.m16n8k16.row.col.f32.bf16.bf16.f32 "
        "{%0,%1,%2,%3}, {%4,%5,%6,%7}, {%8,%9}, {%0,%1,%2,%3};"
        : "+f"(c[0]), "+f"(c[1]), "+f"(c[2]), "+f"(c[3])
        : "r"(a[0]), "r"(a[1]), "r"(a[2]), "r"(a[3]), "r"(b[0]), "r"(b[1]));
}

__device__ __forceinline__ void cpasync16(uint32_t dst, const void* src) {
    asm volatile("cp.async.cg.shared.global [%0], [%1], 16;" :: "r"(dst), "l"(src));
}

// fp32 pair -> bf16 hi + bf16 lo (residual) packed as b32
__device__ __forceinline__ void split2(float x, float y, uint32_t& hi, uint32_t& lo) {
    __nv_bfloat162 h = __floats2bfloat162_rn(x, y);
    float rx = x - __bfloat162float(__low2bfloat16(h));
    float ry = y - __bfloat162float(__high2bfloat16(h));
    __nv_bfloat162 l = __floats2bfloat162_rn(rx, ry);
    hi = *(uint32_t*)&h;
    lo = *(uint32_t*)&l;
}

// ---------------------------------------------------------------------------
// Fused weight transpose + split for all 6 weight matrices (one launch)
// ---------------------------------------------------------------------------
__global__ void wsplit_all(const float* __restrict__ w0, const float* __restrict__ w1,
                           const float* __restrict__ w2, const float* __restrict__ w3,
                           const float* __restrict__ w4, const float* __restrict__ w5,
                           __nv_bfloat16* __restrict__ hi, __nv_bfloat16* __restrict__ lo)
{
    int idx = blockIdx.x * 256 + threadIdx.x;
    if (idx >= 262144) return;
    const float* W; int K, N, local;
    if      (idx < 49152)  { W = w0; K = 128; N = 384; local = idx; }
    else if (idx < 65536)  { W = w1; K = 128; N = 128; local = idx - 49152; }
    else if (idx < 114688) { W = w2; K = 128; N = 384; local = idx - 65536; }
    else if (idx < 131072) { W = w3; K = 128; N = 128; local = idx - 114688; }
    else if (idx < 196608) { W = w4; K = 128; N = 512; local = idx - 131072; }
    else                   { W = w5; K = 512; N = 128; local = idx - 196608; }
    int n = local / K, k = local % K;
    float v = W[(size_t)k * N + n];
    __nv_bfloat16 h = __float2bfloat16(v);
    hi[idx] = h;
    lo[idx] = __float2bfloat16(v - __bfloat162float(h));
}

// ---------------------------------------------------------------------------
// LayerNorm: one warp per token row of 128 floats; outputs bf16 hi/lo
// ---------------------------------------------------------------------------
__global__ void ln_kernel(const float* __restrict__ X,
                          const float* __restrict__ s,
                          const float* __restrict__ b,
                          __nv_bfloat16* __restrict__ Ohi,
                          __nv_bfloat16* __restrict__ Olo, int rows)
{
    int gw   = (blockIdx.x * blockDim.x + threadIdx.x) >> 5;
    int lane = threadIdx.x & 31;
    if (gw >= rows) return;
    float4 v = ((const float4*)(X + (size_t)gw * 128))[lane];
    float sum = v.x + v.y + v.z + v.w;
    #pragma unroll
    for (int o = 16; o; o >>= 1) sum += __shfl_xor_sync(0xffffffffu, sum, o);
    float mean = sum * (1.0f / 128.0f);
    float dx = (v.x - mean) * (v.x - mean) + (v.y - mean) * (v.y - mean)
             + (v.z - mean) * (v.z - mean) + (v.w - mean) * (v.w - mean);
    #pragma unroll
    for (int o = 16; o; o >>= 1) dx += __shfl_xor_sync(0xffffffffu, dx, o);
    float rstd = rsqrtf(dx * (1.0f / 128.0f) + EPS);
    float4 sv = ((const float4*)s)[lane];
    float4 bv = ((const float4*)b)[lane];
    float o0 = (v.x - mean) * rstd * sv.x + bv.x;
    float o1 = (v.y - mean) * rstd * sv.y + bv.y;
    float o2 = (v.z - mean) * rstd * sv.z + bv.z;
    float o3 = (v.w - mean) * rstd * sv.w + bv.w;
    uint32_t h0, l0, h1, l1;
    split2(o0, o1, h0, l0);
    split2(o2, o3, h1, l1);
    uint2 hv; hv.x = h0; hv.y = h1;
    uint2 lv; lv.x = l0; lv.y = l1;
    ((uint2*)(Ohi + (size_t)gw * 128))[lane] = hv;
    ((uint2*)(Olo + (size_t)gw * 128))[lane] = lv;
}

// ---------------------------------------------------------------------------
// Pre-split bf16 tensor-core GEMM: C = Ahi/lo @ (Bhi/lo)^T + bias (+res)(gelu)
// CTA 128x128, BK=32, 256 threads (8 warps 4Mx2N, warp tile 32x64).
// Double-buffered cp.async; 2 CTAs/SM (regs capped at 128; B frags consumed
// per np-tile to keep live registers within budget).
// EPI: 0 = bias->fp32 C; 1 = bias+res->fp32 C; 2 = bias+GELU->bf16 hi/lo C
// ---------------------------------------------------------------------------
constexpr int ST = 40;                 // smem row stride in bf16 (80B)
constexpr int BUF = 128 * ST * 2;      // 10240 B per operand buffer
constexpr int STAGE = 4 * BUF;         // 40960 B per stage
constexpr int GSMEM = 2 * STAGE;       // 81920 B total

template <int EPI>
__global__ __launch_bounds__(256, 2)
void gemm_bf(const __nv_bfloat16* __restrict__ Ahi, const __nv_bfloat16* __restrict__ Alo,
             const __nv_bfloat16* __restrict__ Bhi, const __nv_bfloat16* __restrict__ Blo,
             const float* __restrict__ bias, const float* __restrict__ Res,
             float* __restrict__ C,
             __nv_bfloat16* __restrict__ Chi, __nv_bfloat16* __restrict__ Clo,
             int Nc, int K, int Mreal)
{
    extern __shared__ char smem[];
    const int tid  = threadIdx.x;
    const int lane = tid & 31;
    const int wid  = tid >> 5;
    const int wm   = wid & 3;
    const int wn   = wid >> 2;
    const int m0   = blockIdx.y * 128;
    const int gn0  = blockIdx.x * 128;
    const uint32_t sbase = s2u(smem);

    float acc[2][8][4] = {};
    const int nch = K / 32;

    const int asub = lane >> 3;
    const int arow = (lane & 7) + (asub & 1) * 8;
    const int acol = (asub >> 1) * 8;
    const int bnof = (lane & 7) + ((lane >> 3) >> 1) * 8;
    const int bkof = ((lane >> 3) & 1) * 8;

    auto issue = [&](int c) {
        const int k0 = c * 32;
        const uint32_t st = sbase + (c & 1) * STAGE;
        #pragma unroll
        for (int i = 0; i < 2; i++) {
            int u = i * 256 + tid, row = u >> 2, g = u & 3;
            size_t go = (size_t)(m0 + row) * K + k0 + g * 8;
            uint32_t dst = st + row * 80 + g * 16;
            cpasync16(dst,       Ahi + go);
            cpasync16(dst + BUF, Alo + go);
        }
        #pragma unroll
        for (int i = 0; i < 2; i++) {
            int u = i * 256 + tid, n = u >> 2, g = u & 3;
            size_t go = (size_t)(gn0 + n) * K + k0 + g * 8;
            uint32_t dst = st + 2 * BUF + n * 80 + g * 16;
            cpasync16(dst,       Bhi + go);
            cpasync16(dst + BUF, Blo + go);
        }
        asm volatile("cp.async.commit_group;");
    };

    issue(0);
    for (int c = 0; c < nch; c++) {
        if (c + 1 < nch) {
            issue(c + 1);
            asm volatile("cp.async.wait_group 1;");
        } else {
            asm volatile("cp.async.wait_group 0;");
        }
        __syncthreads();

        const uint32_t aH = sbase + (c & 1) * STAGE;
        const uint32_t aL = aH + BUF;
        const uint32_t bH = aH + 2 * BUF;
        const uint32_t bL = aH + 3 * BUF;

        #pragma unroll
        for (int ks = 0; ks < 2; ks++) {
            uint32_t ah[2][4], al[2][4];
            #pragma unroll
            for (int mt = 0; mt < 2; mt++) {
                uint32_t off = (uint32_t)((wm * 32 + mt * 16 + arow) * ST + ks * 16 + acol) * 2;
                ldsm4(ah[mt][0], ah[mt][1], ah[mt][2], ah[mt][3], aH + off);
                ldsm4(al[mt][0], al[mt][1], al[mt][2], al[mt][3], aL + off);
            }
            // B fragments loaded per np-tile and consumed immediately
            #pragma unroll
            for (int np = 0; np < 4; np++) {
                uint32_t off = (uint32_t)((wn * 64 + np * 16 + bnof) * ST + ks * 16 + bkof) * 2;
                uint32_t bh[2][2], bl[2][2];
                ldsm4(bh[0][0], bh[0][1], bh[1][0], bh[1][1], bH + off);
                ldsm4(bl[0][0], bl[0][1], bl[1][0], bl[1][1], bL + off);
                #pragma unroll
                for (int half = 0; half < 2; half++) {
                    int nt = np * 2 + half;
                    #pragma unroll
                    for (int mt = 0; mt < 2; mt++) {
                        mma_bf16(acc[mt][nt], ah[mt], bh[half]);
                        mma_bf16(acc[mt][nt], ah[mt], bl[half]);
                        mma_bf16(acc[mt][nt], al[mt], bh[half]);
                    }
                }
            }
        }
        __syncthreads();
    }

    const int r0 = m0 + wm * 32 + (lane >> 2);
    const int c0 = gn0 + wn * 64 + (lane & 3) * 2;
    #pragma unroll
    for (int mt = 0; mt < 2; mt++) {
        #pragma unroll
        for (int half = 0; half < 2; half++) {
            int r = r0 + mt * 16 + half * 8;
            if (r < Mreal) {
                #pragma unroll
                for (int nt = 0; nt < 8; nt++) {
                    int cc = c0 + nt * 8;
                    float v0 = acc[mt][nt][half * 2 + 0] + bias[cc];
                    float v1 = acc[mt][nt][half * 2 + 1] + bias[cc + 1];
                    if (EPI == 1) {
                        float2 rv = *(const float2*)(Res + (size_t)r * Nc + cc);
                        v0 += rv.x; v1 += rv.y;
                    }
                    if (EPI == 2) {
                        v0 = 0.5f * v0 * (1.0f + erff(v0 * 0.70710678118654752f));
                        v1 = 0.5f * v1 * (1.0f + erff(v1 * 0.70710678118654752f));
                        uint32_t h, l;
                        split2(v0, v1, h, l);
                        *(uint32_t*)(Chi + (size_t)r * Nc + cc) = h;
                        *(uint32_t*)(Clo + (size_t)r * Nc + cc) = l;
                    } else {
                        float2 o; o.x = v0; o.y = v1;
                        *(float2*)(C + (size_t)r * Nc + cc) = o;
                    }
                }
            }
        }
    }
}

// ---------------------------------------------------------------------------
// Temporal attention v2: block per (b,n,head), L=48, HD=16; bf16 hi/lo out.
// ---------------------------------------------------------------------------
__global__ __launch_bounds__(64, 8)
void attn_temporal(const float* __restrict__ qkv,
                   __nv_bfloat16* __restrict__ Ohi, __nv_bfloat16* __restrict__ Olo)
{
    int h  = blockIdx.x & 7;
    int bn = blockIdx.x >> 3;
    __shared__ float q[48][20], k[48][20], v[48][20];
    __shared__ float sc[48][50];
    int tid = threadIdx.x;

    size_t base = (size_t)bn * 48 * 384 + h * 16;
    #pragma unroll 1
    for (int i = tid; i < 48 * 4; i += 64) {
        int row = i >> 2, seg = i & 3;
        const float* p = qkv + base + (size_t)row * 384;
        *(float4*)&q[row][seg * 4] = ((const float4*)(p))[seg];
        *(float4*)&k[row][seg * 4] = ((const float4*)(p + 128))[seg];
        *(float4*)&v[row][seg * 4] = ((const float4*)(p + 256))[seg];
    }
    __syncthreads();

    #pragma unroll 1
    for (int i = tid; i < 48 * 48; i += 64) {
        int qi = i / 48, ki = i % 48;
        float4 a0 = *(const float4*)&q[qi][0],  a1 = *(const float4*)&q[qi][4];
        float4 a2 = *(const float4*)&q[qi][8],  a3 = *(const float4*)&q[qi][12];
        float4 b0 = *(const float4*)&k[ki][0],  b1 = *(const float4*)&k[ki][4];
        float4 b2 = *(const float4*)&k[ki][8],  b3 = *(const float4*)&k[ki][12];
        float s = a0.x*b0.x + a0.y*b0.y + a0.z*b0.z + a0.w*b0.w
                + a1.x*b1.x + a1.y*b1.y + a1.z*b1.z + a1.w*b1.w
                + a2.x*b2.x + a2.y*b2.y + a2.z*b2.z + a2.w*b2.w
                + a3.x*b3.x + a3.y*b3.y + a3.z*b3.z + a3.w*b3.w;
        sc[qi][ki] = s * SCALE;
    }
    __syncthreads();

    if (tid < 48) {
        float mx = -3.4e38f;
        #pragma unroll 1
        for (int j = 0; j < 48; j++) mx = fmaxf(mx, sc[tid][j]);
        float l = 0.f;
        #pragma unroll 1
        for (int j = 0; j < 48; j++) {
            float p = __expf(sc[tid][j] - mx);
            sc[tid][j] = p; l += p;
        }
        float inv = 1.0f / l;
        #pragma unroll 1
        for (int j = 0; j < 48; j++) sc[tid][j] *= inv;
    }
    __syncthreads();

    #pragma unroll 1
    for (int i = tid; i < 48 * 4; i += 64) {
        int qi = i >> 2, seg = i & 3;
        float4 o = make_float4(0.f, 0.f, 0.f, 0.f);
        #pragma unroll 8
        for (int kk = 0; kk < 48; kk++) {
            float w = sc[qi][kk];
            float4 vv = *(const float4*)&v[kk][seg * 4];
            o.x = fmaf(w, vv.x, o.x);
            o.y = fmaf(w, vv.y, o.y);
            o.z = fmaf(w, vv.z, o.z);
            o.w = fmaf(w, vv.w, o.w);
        }
        uint32_t h0, l0, h1, l1;
        split2(o.x, o.y, h0, l0);
        split2(o.z, o.w, h1, l1);
        size_t off = (size_t)(bn * 48 + qi) * 128 + h * 16 + seg * 4;
        uint2 hv; hv.x = h0; hv.y = h1;
        uint2 lv; lv.x = l0; lv.y = l1;
        *(uint2*)(Ohi + off) = hv;
        *(uint2*)(Olo + off) = lv;
    }
}

// ---------------------------------------------------------------------------
// Spatial attention (scalar flash, known-good): block per (b,t,head), L=325.
// float4 smem reads; mask read as int32; bf16 hi/lo out.
// ---------------------------------------------------------------------------
constexpr int KT = 32;

__global__ __launch_bounds__(352)
void attn_spatial(const float* __restrict__ qkv, const int* __restrict__ mask,
                  __nv_bfloat16* __restrict__ Ohi, __nv_bfloat16* __restrict__ Olo)
{
    int h  = blockIdx.x & 7;
    int bt = blockIdx.x >> 3;
    int t  = bt % Tt, b = bt / Tt;
    int tid = threadIdx.x;
    int nq  = tid;
    bool active = nq < Nn;

    __shared__ float ks[KT][16], vs[KT][16];
    __shared__ int   msk[KT];

    float4 qr[4];
    float4 acc[4];
    #pragma unroll
    for (int i = 0; i < 4; i++) acc[i] = make_float4(0.f, 0.f, 0.f, 0.f);
    float m = -3.4e38f, l = 0.f;

    if (active) {
        const float* p = qkv + ((size_t)(b * Nn + nq) * Tt + t) * 384 + h * 16;
        #pragma unroll
        for (int i = 0; i < 4; i++) qr[i] = ((const float4*)p)[i];
    }

    for (int kt = 0; kt < Nn; kt += KT) {
        int nk = min(KT, Nn - kt);
        __syncthreads();
        if (tid < 128) {
            int r = tid >> 2, seg = tid & 3;
            if (r < nk) {
                const float* p = qkv + ((size_t)(b * Nn + kt + r) * Tt + t) * 384 + 128 + h * 16;
                ((float4*)ks[r])[seg] = ((const float4*)p)[seg];
            }
        } else if (tid < 256) {
            int r = (tid - 128) >> 2, seg = tid & 3;
            if (r < nk) {
                const float* p = qkv + ((size_t)(b * Nn + kt + r) * Tt + t) * 384 + 256 + h * 16;
                ((float4*)vs[r])[seg] = ((const float4*)p)[seg];
            }
        } else if (tid < 256 + KT) {
            int j = tid - 256;
            msk[j] = (kt + j < Nn) ? (mask[b * Nn + kt + j] != 0 ? 1 : 0) : 0;
        }
        __syncthreads();

        if (active) {
            float sarr[KT];
            #pragma unroll
            for (int j = 0; j < KT; j++) {
                const float4* k4 = (const float4*)ks[j];
                float4 b0 = k4[0], b1 = k4[1], b2 = k4[2], b3 = k4[3];
                float d = qr[0].x*b0.x + qr[0].y*b0.y + qr[0].z*b0.z + qr[0].w*b0.w
                        + qr[1].x*b1.x + qr[1].y*b1.y + qr[1].z*b1.z + qr[1].w*b1.w
                        + qr[2].x*b2.x + qr[2].y*b2.y + qr[2].z*b2.z + qr[2].w*b2.w
                        + qr[3].x*b3.x + qr[3].y*b3.y + qr[3].z*b3.z + qr[3].w*b3.w;
                sarr[j] = msk[j] ? d * SCALE : -3.4e38f;
            }
            float tm = -3.4e38f;
            #pragma unroll
            for (int j = 0; j < KT; j++) tm = fmaxf(tm, sarr[j]);
            float mnew = fmaxf(m, tm);
            float corr = __expf(m - mnew);
            l *= corr;
            #pragma unroll
            for (int i = 0; i < 4; i++) {
                acc[i].x *= corr; acc[i].y *= corr; acc[i].z *= corr; acc[i].w *= corr;
            }
            #pragma unroll
            for (int j = 0; j < KT; j++) {
                float p = (sarr[j] > -3.0e38f) ? __expf(sarr[j] - mnew) : 0.f;
                l += p;
                const float4* v4 = (const float4*)vs[j];
                #pragma unroll
                for (int i = 0; i < 4; i++) {
                    float4 vv = v4[i];
                    acc[i].x = fmaf(p, vv.x, acc[i].x);
                    acc[i].y = fmaf(p, vv.y, acc[i].y);
                    acc[i].z = fmaf(p, vv.z, acc[i].z);
                    acc[i].w = fmaf(p, vv.w, acc[i].w);
                }
            }
            m = mnew;
        }
    }

    if (active) {
        float inv = 1.0f / l;
        size_t off = (size_t)(b * Nn + nq) * Tt + t;
        __nv_bfloat16* oh = Ohi + off * 128 + h * 16;
        __nv_bfloat16* ol = Olo + off * 128 + h * 16;
        #pragma unroll
        for (int i = 0; i < 4; i++) {
            float o0 = acc[i].x * inv, o1 = acc[i].y * inv;
            float o2 = acc[i].z * inv, o3 = acc[i].w * inv;
            uint32_t h0, l0, h1, l1;
            split2(o0, o1, h0, l0);
            split2(o2, o3, h1, l1);
            uint2 hv; hv.x = h0; hv.y = h1;
            uint2 lv; lv.x = l0; lv.y = l1;
            *(uint2*)(oh + i * 4) = hv;
            *(uint2*)(ol + i * 4) = lv;
        }
    }
}

// ---------------------------------------------------------------------------
// Orchestration
// ---------------------------------------------------------------------------
extern "C" void kernel_launch(void* const* d_in, const int* in_sizes, int n_in,
                              void* d_out, int out_size)
{
    const float* x       = (const float*)d_in[0];
    const int*   mask    = (const int*)  d_in[1];
    const float* ln1_s   = (const float*)d_in[2];
    const float* ln1_b   = (const float*)d_in[3];
    const float* tqkv_w  = (const float*)d_in[4];
    const float* tqkv_b  = (const float*)d_in[5];
    const float* tproj_w = (const float*)d_in[6];
    const float* tproj_b = (const float*)d_in[7];
    const float* ln2_s   = (const float*)d_in[8];
    const float* ln2_b   = (const float*)d_in[9];
    const float* sqkv_w  = (const float*)d_in[10];
    const float* sqkv_b  = (const float*)d_in[11];
    const float* sproj_w = (const float*)d_in[12];
    const float* sproj_b = (const float*)d_in[13];
    const float* ln3_s   = (const float*)d_in[14];
    const float* ln3_b   = (const float*)d_in[15];
    const float* fw1     = (const float*)d_in[16];
    const float* fb1     = (const float*)d_in[17];
    const float* fw2     = (const float*)d_in[18];
    const float* fb2     = (const float*)d_in[19];
    float* out = (float*)d_out;

    float *qkv, *x1, *x2;
    __nv_bfloat16 *hh, *hl, *ah, *al, *fh, *fl, *wh, *wl;
    cudaGetSymbolAddress((void**)&qkv, g_qkv);
    cudaGetSymbolAddress((void**)&x1,  g_x1);
    cudaGetSymbolAddress((void**)&x2,  g_x2);
    cudaGetSymbolAddress((void**)&hh,  g_hh);
    cudaGetSymbolAddress((void**)&hl,  g_hl);
    cudaGetSymbolAddress((void**)&ah,  g_ah);
    cudaGetSymbolAddress((void**)&al,  g_al);
    cudaGetSymbolAddress((void**)&fh,  g_fh);
    cudaGetSymbolAddress((void**)&fl,  g_fl);
    cudaGetSymbolAddress((void**)&wh,  g_wh);
    cudaGetSymbolAddress((void**)&wl,  g_wl);

    cudaFuncSetAttribute(gemm_bf<0>, cudaFuncAttributeMaxDynamicSharedMemorySize, GSMEM);
    cudaFuncSetAttribute(gemm_bf<1>, cudaFuncAttributeMaxDynamicSharedMemorySize, GSMEM);
    cudaFuncSetAttribute(gemm_bf<2>, cudaFuncAttributeMaxDynamicSharedMemorySize, GSMEM);

    // one-time weight transpose + split (single launch)
    wsplit_all<<<1024, 256>>>(tqkv_w, tproj_w, sqkv_w, sproj_w, fw1, fw2, wh, wl);

    const int ln_grid = (M + 7) / 8;
    dim3 g_qkv_grid(3, MT);    // N=384
    dim3 g_d_grid  (1, MT);    // N=128
    dim3 g_ffn1    (4, MT);    // N=512

    // ---- temporal branch ----
    ln_kernel<<<ln_grid, 256>>>(x, ln1_s, ln1_b, hh, hl, M);
    gemm_bf<0><<<g_qkv_grid, 256, GSMEM>>>(hh, hl, wh + W_TQKV, wl + W_TQKV,
                                           tqkv_b, nullptr, qkv, nullptr, nullptr, 384, 128, M);
    attn_temporal<<<Bb * Nn * Hh, 64>>>(qkv, ah, al);
    gemm_bf<1><<<g_d_grid, 256, GSMEM>>>(ah, al, wh + W_TPRJ, wl + W_TPRJ,
                                         tproj_b, x, x1, nullptr, nullptr, 128, 128, M);

    // ---- spatial branch ----
    ln_kernel<<<ln_grid, 256>>>(x1, ln2_s, ln2_b, hh, hl, M);
    gemm_bf<0><<<g_qkv_grid, 256, GSMEM>>>(hh, hl, wh + W_SQKV, wl + W_SQKV,
                                           sqkv_b, nullptr, qkv, nullptr, nullptr, 384, 128, M);
    attn_spatial<<<Bb * Tt * Hh, 352>>>(qkv, mask, ah, al);
    gemm_bf<1><<<g_d_grid, 256, GSMEM>>>(ah, al, wh + W_SPRJ, wl + W_SPRJ,
                                         sproj_b, x1, x2, nullptr, nullptr, 128, 128, M);

    // ---- FFN ----
    ln_kernel<<<ln_grid, 256>>>(x2, ln3_s, ln3_b, hh, hl, M);
    gemm_bf<2><<<g_ffn1, 256, GSMEM>>>(hh, hl, wh + W_FW1, wl + W_FW1,
                                       fb1, nullptr, nullptr, fh, fl, 512, 128, M);
    gemm_bf<1><<<g_d_grid, 256, GSMEM>>>(fh, fl, wh + W_FW2, wl + W_FW2,
                                         fb2, x2, out, nullptr, nullptr, 128, 512, M);
}

// round 14
// speedup vs baseline: 1.7157x; 1.2145x over previous
#include <cuda_runtime.h>
#include <cuda_bf16.h>
#include <math.h>
#include <stdint.h>

// Problem constants
constexpr int Bb = 4, Nn = 325, Tt = 48, Hh = 8;
constexpr int M  = Bb * Nn * Tt;      // 62400 tokens
constexpr int MT = 488;               // M tiles of 128
constexpr int M_PAD = MT * 128;       // 62464
constexpr float SCALE = 0.25f;        // HD^-0.5, HD=16
constexpr float EPS = 1e-5f;

// Scratch (device globals, zero-initialized; pad rows [M, M_PAD) never written)
__device__ float g_qkv[M_PAD * 384];
__device__ float g_x1 [M_PAD * 128];
__device__ float g_x2 [M_PAD * 128];
__device__ __nv_bfloat16 g_hh[M_PAD * 128], g_hl[M_PAD * 128];   // LN out hi/lo
__device__ __nv_bfloat16 g_ah[M_PAD * 128], g_al[M_PAD * 128];   // attn out hi/lo
__device__ __nv_bfloat16 g_fh[M_PAD * 512], g_fl[M_PAD * 512];   // ffn1 out hi/lo
__device__ __nv_bfloat16 g_wh[262144],      g_wl[262144];        // weights^T hi/lo

// Weight segment offsets in g_wh/g_wl ([N,K] layout each)
constexpr int W_TQKV = 0;        // 384x128
constexpr int W_TPRJ = 49152;    // 128x128
constexpr int W_SQKV = 65536;    // 384x128
constexpr int W_SPRJ = 114688;   // 128x128
constexpr int W_FW1  = 131072;   // 512x128
constexpr int W_FW2  = 196608;   // 128x512

// ---------------------------------------------------------------------------
// Baseline-PTX helpers (sm_80-class: mma.sync, ldmatrix, cp.async)
// ---------------------------------------------------------------------------
__device__ __forceinline__ uint32_t s2u(const void* p) {
    uint32_t a;
    asm("{ .reg .u64 t; cvta.to.shared.u64 t, %1; cvt.u32.u64 %0, t; }"
        : "=r"(a) : "l"(p));
    return a;
}

__device__ __forceinline__ void ldsm4(uint32_t& r0, uint32_t& r1,
                                      uint32_t& r2, uint32_t& r3, uint32_t a) {
    asm volatile("ldmatrix.sync.aligned.m8n8.x4.shared.b16 {%0,%1,%2,%3}, [%4];"
                 : "=r"(r0), "=r"(r1), "=r"(r2), "=r"(r3) : "r"(a));
}

__device__ __forceinline__ void mma_bf16(float* c, const uint32_t* a, const uint32_t* b) {
    asm volatile(
        "mma.sync.aligned.m16n8k16.row.col.f32.bf16.bf16.f32 "
        "{%0,%1,%2,%3}, {%4,%5,%6,%7}, {%8,%9}, {%0,%1,%2,%3};"
        : "+f"(c[0]), "+f"(c[1]), "+f"(c[2]), "+f"(c[3])
        : "r"(a[0]), "r"(a[1]), "r"(a[2]), "r"(a[3]), "r"(b[0]), "r"(b[1]));
}

__device__ __forceinline__ void cpasync16(uint32_t dst, const void* src) {
    asm volatile("cp.async.cg.shared.global [%0], [%1], 16;" :: "r"(dst), "l"(src));
}

// fp32 pair -> bf16 hi + bf16 lo (residual) packed as b32
__device__ __forceinline__ void split2(float x, float y, uint32_t& hi, uint32_t& lo) {
    __nv_bfloat162 h = __floats2bfloat162_rn(x, y);
    float rx = x - __bfloat162float(__low2bfloat16(h));
    float ry = y - __bfloat162float(__high2bfloat16(h));
    __nv_bfloat162 l = __floats2bfloat162_rn(rx, ry);
    hi = *(uint32_t*)&h;
    lo = *(uint32_t*)&l;
}

// token row (b,n,t) -> transposed row (b,t,n). Used only on epilogue WRITES.
__device__ __forceinline__ int tok2trans(int r) {
    int b = r / 15600, rr = r % 15600;
    int n = rr / 48, t = rr % 48;
    return b * 15600 + t * 325 + n;
}

// ---------------------------------------------------------------------------
// Fused weight transpose + split for all 6 weight matrices (one launch)
// ---------------------------------------------------------------------------
__global__ void wsplit_all(const float* __restrict__ w0, const float* __restrict__ w1,
                           const float* __restrict__ w2, const float* __restrict__ w3,
                           const float* __restrict__ w4, const float* __restrict__ w5,
                           __nv_bfloat16* __restrict__ hi, __nv_bfloat16* __restrict__ lo)
{
    int idx = blockIdx.x * 256 + threadIdx.x;
    if (idx >= 262144) return;
    const float* W; int K, N, local;
    if      (idx < 49152)  { W = w0; K = 128; N = 384; local = idx; }
    else if (idx < 65536)  { W = w1; K = 128; N = 128; local = idx - 49152; }
    else if (idx < 114688) { W = w2; K = 128; N = 384; local = idx - 65536; }
    else if (idx < 131072) { W = w3; K = 128; N = 128; local = idx - 114688; }
    else if (idx < 196608) { W = w4; K = 128; N = 512; local = idx - 131072; }
    else                   { W = w5; K = 512; N = 128; local = idx - 196608; }
    int n = local / K, k = local % K;
    float v = W[(size_t)k * N + n];
    __nv_bfloat16 h = __float2bfloat16(v);
    hi[idx] = h;
    lo[idx] = __float2bfloat16(v - __bfloat162float(h));
}

// ---------------------------------------------------------------------------
// LayerNorm: one warp per token row of 128 floats; outputs bf16 hi/lo
// ---------------------------------------------------------------------------
__global__ void ln_kernel(const float* __restrict__ X,
                          const float* __restrict__ s,
                          const float* __restrict__ b,
                          __nv_bfloat16* __restrict__ Ohi,
                          __nv_bfloat16* __restrict__ Olo, int rows)
{
    int gw   = (blockIdx.x * blockDim.x + threadIdx.x) >> 5;
    int lane = threadIdx.x & 31;
    if (gw >= rows) return;
    float4 v = ((const float4*)(X + (size_t)gw * 128))[lane];
    float sum = v.x + v.y + v.z + v.w;
    #pragma unroll
    for (int o = 16; o; o >>= 1) sum += __shfl_xor_sync(0xffffffffu, sum, o);
    float mean = sum * (1.0f / 128.0f);
    float dx = (v.x - mean) * (v.x - mean) + (v.y - mean) * (v.y - mean)
             + (v.z - mean) * (v.z - mean) + (v.w - mean) * (v.w - mean);
    #pragma unroll
    for (int o = 16; o; o >>= 1) dx += __shfl_xor_sync(0xffffffffu, dx, o);
    float rstd = rsqrtf(dx * (1.0f / 128.0f) + EPS);
    float4 sv = ((const float4*)s)[lane];
    float4 bv = ((const float4*)b)[lane];
    float o0 = (v.x - mean) * rstd * sv.x + bv.x;
    float o1 = (v.y - mean) * rstd * sv.y + bv.y;
    float o2 = (v.z - mean) * rstd * sv.z + bv.z;
    float o3 = (v.w - mean) * rstd * sv.w + bv.w;
    uint32_t h0, l0, h1, l1;
    split2(o0, o1, h0, l0);
    split2(o2, o3, h1, l1);
    uint2 hv; hv.x = h0; hv.y = h1;
    uint2 lv; lv.x = l0; lv.y = l1;
    ((uint2*)(Ohi + (size_t)gw * 128))[lane] = hv;
    ((uint2*)(Olo + (size_t)gw * 128))[lane] = lv;
}

// ---------------------------------------------------------------------------
// Pre-split bf16 tensor-core GEMM: C = Ahi/lo @ (Bhi/lo)^T + bias (+res)(gelu)
// CTA 128x128, BK=32, 256 threads; double-buffered cp.async; 2 CTAs/SM.
// EPI: 0 = bias->fp32 C; 1 = bias+res->fp32 C; 2 = bias+GELU->bf16 hi/lo C
// WPERM: 1 = epilogue writes C row tok2trans(r) (loads stay coalesced)
// ---------------------------------------------------------------------------
constexpr int ST = 40;                 // smem row stride in bf16 (80B)
constexpr int BUF = 128 * ST * 2;      // 10240 B per operand buffer
constexpr int STAGE = 4 * BUF;         // 40960 B per stage
constexpr int GSMEM = 2 * STAGE;       // 81920 B total

template <int EPI, int WPERM = 0>
__global__ __launch_bounds__(256, 2)
void gemm_bf(const __nv_bfloat16* __restrict__ Ahi, const __nv_bfloat16* __restrict__ Alo,
             const __nv_bfloat16* __restrict__ Bhi, const __nv_bfloat16* __restrict__ Blo,
             const float* __restrict__ bias, const float* __restrict__ Res,
             float* __restrict__ C,
             __nv_bfloat16* __restrict__ Chi, __nv_bfloat16* __restrict__ Clo,
             int Nc, int K, int Mreal)
{
    extern __shared__ char smem[];
    const int tid  = threadIdx.x;
    const int lane = tid & 31;
    const int wid  = tid >> 5;
    const int wm   = wid & 3;
    const int wn   = wid >> 2;
    const int m0   = blockIdx.y * 128;
    const int gn0  = blockIdx.x * 128;
    const uint32_t sbase = s2u(smem);

    float acc[2][8][4] = {};
    const int nch = K / 32;

    const int asub = lane >> 3;
    const int arow = (lane & 7) + (asub & 1) * 8;
    const int acol = (asub >> 1) * 8;
    const int bnof = (lane & 7) + ((lane >> 3) >> 1) * 8;
    const int bkof = ((lane >> 3) & 1) * 8;

    auto issue = [&](int c) {
        const int k0 = c * 32;
        const uint32_t st = sbase + (c & 1) * STAGE;
        #pragma unroll
        for (int i = 0; i < 2; i++) {
            int u = i * 256 + tid, row = u >> 2, g = u & 3;
            size_t go = (size_t)(m0 + row) * K + k0 + g * 8;
            uint32_t dst = st + row * 80 + g * 16;
            cpasync16(dst,       Ahi + go);
            cpasync16(dst + BUF, Alo + go);
        }
        #pragma unroll
        for (int i = 0; i < 2; i++) {
            int u = i * 256 + tid, n = u >> 2, g = u & 3;
            size_t go = (size_t)(gn0 + n) * K + k0 + g * 8;
            uint32_t dst = st + 2 * BUF + n * 80 + g * 16;
            cpasync16(dst,       Bhi + go);
            cpasync16(dst + BUF, Blo + go);
        }
        asm volatile("cp.async.commit_group;");
    };

    issue(0);
    for (int c = 0; c < nch; c++) {
        if (c + 1 < nch) {
            issue(c + 1);
            asm volatile("cp.async.wait_group 1;");
        } else {
            asm volatile("cp.async.wait_group 0;");
        }
        __syncthreads();

        const uint32_t aH = sbase + (c & 1) * STAGE;
        const uint32_t aL = aH + BUF;
        const uint32_t bH = aH + 2 * BUF;
        const uint32_t bL = aH + 3 * BUF;

        #pragma unroll
        for (int ks = 0; ks < 2; ks++) {
            uint32_t ah[2][4], al[2][4];
            #pragma unroll
            for (int mt = 0; mt < 2; mt++) {
                uint32_t off = (uint32_t)((wm * 32 + mt * 16 + arow) * ST + ks * 16 + acol) * 2;
                ldsm4(ah[mt][0], ah[mt][1], ah[mt][2], ah[mt][3], aH + off);
                ldsm4(al[mt][0], al[mt][1], al[mt][2], al[mt][3], aL + off);
            }
            #pragma unroll
            for (int np = 0; np < 4; np++) {
                uint32_t off = (uint32_t)((wn * 64 + np * 16 + bnof) * ST + ks * 16 + bkof) * 2;
                uint32_t bh[2][2], bl[2][2];
                ldsm4(bh[0][0], bh[0][1], bh[1][0], bh[1][1], bH + off);
                ldsm4(bl[0][0], bl[0][1], bl[1][0], bl[1][1], bL + off);
                #pragma unroll
                for (int half = 0; half < 2; half++) {
                    int nt = np * 2 + half;
                    #pragma unroll
                    for (int mt = 0; mt < 2; mt++) {
                        mma_bf16(acc[mt][nt], ah[mt], bh[half]);
                        mma_bf16(acc[mt][nt], ah[mt], bl[half]);
                        mma_bf16(acc[mt][nt], al[mt], bh[half]);
                    }
                }
            }
        }
        __syncthreads();
    }

    const int r0 = m0 + wm * 32 + (lane >> 2);
    const int c0 = gn0 + wn * 64 + (lane & 3) * 2;
    #pragma unroll
    for (int mt = 0; mt < 2; mt++) {
        #pragma unroll
        for (int half = 0; half < 2; half++) {
            int r = r0 + mt * 16 + half * 8;
            if (r < Mreal) {
                int wr = (WPERM == 1) ? tok2trans(r) : r;
                #pragma unroll
                for (int nt = 0; nt < 8; nt++) {
                    int cc = c0 + nt * 8;
                    float v0 = acc[mt][nt][half * 2 + 0] + bias[cc];
                    float v1 = acc[mt][nt][half * 2 + 1] + bias[cc + 1];
                    if (EPI == 1) {
                        float2 rv = *(const float2*)(Res + (size_t)r * Nc + cc);
                        v0 += rv.x; v1 += rv.y;
                    }
                    if (EPI == 2) {
                        v0 = 0.5f * v0 * (1.0f + erff(v0 * 0.70710678118654752f));
                        v1 = 0.5f * v1 * (1.0f + erff(v1 * 0.70710678118654752f));
                        uint32_t h, l;
                        split2(v0, v1, h, l);
                        *(uint32_t*)(Chi + (size_t)wr * Nc + cc) = h;
                        *(uint32_t*)(Clo + (size_t)wr * Nc + cc) = l;
                    } else {
                        float2 o; o.x = v0; o.y = v1;
                        *(float2*)(C + (size_t)wr * Nc + cc) = o;
                    }
                }
            }
        }
    }
}

// ---------------------------------------------------------------------------
// Temporal attention v2: block per (b,n,head), L=48, HD=16; bf16 hi/lo out.
// ---------------------------------------------------------------------------
__global__ __launch_bounds__(64, 8)
void attn_temporal(const float* __restrict__ qkv,
                   __nv_bfloat16* __restrict__ Ohi, __nv_bfloat16* __restrict__ Olo)
{
    int h  = blockIdx.x & 7;
    int bn = blockIdx.x >> 3;
    __shared__ float q[48][20], k[48][20], v[48][20];
    __shared__ float sc[48][50];
    int tid = threadIdx.x;

    size_t base = (size_t)bn * 48 * 384 + h * 16;
    #pragma unroll 1
    for (int i = tid; i < 48 * 4; i += 64) {
        int row = i >> 2, seg = i & 3;
        const float* p = qkv + base + (size_t)row * 384;
        *(float4*)&q[row][seg * 4] = ((const float4*)(p))[seg];
        *(float4*)&k[row][seg * 4] = ((const float4*)(p + 128))[seg];
        *(float4*)&v[row][seg * 4] = ((const float4*)(p + 256))[seg];
    }
    __syncthreads();

    #pragma unroll 1
    for (int i = tid; i < 48 * 48; i += 64) {
        int qi = i / 48, ki = i % 48;
        float4 a0 = *(const float4*)&q[qi][0],  a1 = *(const float4*)&q[qi][4];
        float4 a2 = *(const float4*)&q[qi][8],  a3 = *(const float4*)&q[qi][12];
        float4 b0 = *(const float4*)&k[ki][0],  b1 = *(const float4*)&k[ki][4];
        float4 b2 = *(const float4*)&k[ki][8],  b3 = *(const float4*)&k[ki][12];
        float s = a0.x*b0.x + a0.y*b0.y + a0.z*b0.z + a0.w*b0.w
                + a1.x*b1.x + a1.y*b1.y + a1.z*b1.z + a1.w*b1.w
                + a2.x*b2.x + a2.y*b2.y + a2.z*b2.z + a2.w*b2.w
                + a3.x*b3.x + a3.y*b3.y + a3.z*b3.z + a3.w*b3.w;
        sc[qi][ki] = s * SCALE;
    }
    __syncthreads();

    if (tid < 48) {
        float mx = -3.4e38f;
        #pragma unroll 1
        for (int j = 0; j < 48; j++) mx = fmaxf(mx, sc[tid][j]);
        float l = 0.f;
        #pragma unroll 1
        for (int j = 0; j < 48; j++) {
            float p = __expf(sc[tid][j] - mx);
            sc[tid][j] = p; l += p;
        }
        float inv = 1.0f / l;
        #pragma unroll 1
        for (int j = 0; j < 48; j++) sc[tid][j] *= inv;
    }
    __syncthreads();

    #pragma unroll 1
    for (int i = tid; i < 48 * 4; i += 64) {
        int qi = i >> 2, seg = i & 3;
        float4 o = make_float4(0.f, 0.f, 0.f, 0.f);
        #pragma unroll 8
        for (int kk = 0; kk < 48; kk++) {
            float w = sc[qi][kk];
            float4 vv = *(const float4*)&v[kk][seg * 4];
            o.x = fmaf(w, vv.x, o.x);
            o.y = fmaf(w, vv.y, o.y);
            o.z = fmaf(w, vv.z, o.z);
            o.w = fmaf(w, vv.w, o.w);
        }
        uint32_t h0, l0, h1, l1;
        split2(o.x, o.y, h0, l0);
        split2(o.z, o.w, h1, l1);
        size_t off = (size_t)(bn * 48 + qi) * 128 + h * 16 + seg * 4;
        uint2 hv; hv.x = h0; hv.y = h1;
        uint2 lv; lv.x = l0; lv.y = l1;
        *(uint2*)(Ohi + off) = hv;
        *(uint2*)(Olo + off) = lv;
    }
}

// ---------------------------------------------------------------------------
// Spatial attention via mma.sync on TRANSPOSED qkv (rows in (b,t,n) order,
// contiguous 96KB K/V tiles). Math identical to R11-verified version.
// Output written back in TOKEN order (scattered writes, same cost as before).
// ---------------------------------------------------------------------------
__global__ __launch_bounds__(128)
void attn_spatial_mma(const float* __restrict__ qkvT, const int* __restrict__ mask,
                      __nv_bfloat16* __restrict__ Ohi, __nv_bfloat16* __restrict__ Olo)
{
    __shared__ __nv_bfloat16 sQh[128 * 16], sQl[128 * 16];
    __shared__ __nv_bfloat16 sKh[64 * 16],  sKl[64 * 16];
    __shared__ __nv_bfloat16 sVh[16 * 64],  sVl[16 * 64];
    __shared__ float mbias[384];

    const int tid = threadIdx.x, lane = tid & 31, warp = tid >> 5;
    const int qt = blockIdx.x, h = blockIdx.y, z = blockIdx.z;  // z = b*48+t
    const int b = z / Tt, t = z % Tt;
    const int q0 = qt * 128;
    const size_t rowbase = (size_t)z * Nn;

    for (int j = tid; j < 384; j += 128)
        mbias[j] = (j < Nn && mask[b * Nn + j] != 0) ? 0.f : -1e30f;

    for (int i = tid; i < 512; i += 128) {
        int row = i >> 2, seg = i & 3;
        int n = q0 + row;
        float4 v = make_float4(0.f, 0.f, 0.f, 0.f);
        if (n < Nn)
            v = *(const float4*)(qkvT + (rowbase + n) * 384 + h * 16 + seg * 4);
        uint32_t h0, l0, h1, l1;
        split2(v.x, v.y, h0, l0);
        split2(v.z, v.w, h1, l1);
        *(uint32_t*)&sQh[row * 16 + seg * 4]     = h0;
        *(uint32_t*)&sQh[row * 16 + seg * 4 + 2] = h1;
        *(uint32_t*)&sQl[row * 16 + seg * 4]     = l0;
        *(uint32_t*)&sQl[row * 16 + seg * 4 + 2] = l1;
    }
    __syncthreads();

    const int asub = lane >> 3;
    const int arow = (lane & 7) + (asub & 1) * 8;
    const int acol = (asub >> 1) * 8;
    const int bnof = (lane & 7) + ((lane >> 3) >> 1) * 8;
    const int bkof = ((lane >> 3) & 1) * 8;

    uint32_t qh[2][4], ql[2][4];
    const uint32_t qhB = s2u(sQh), qlB = s2u(sQl);
    #pragma unroll
    for (int mt = 0; mt < 2; mt++) {
        uint32_t off = (uint32_t)((warp * 32 + mt * 16 + arow) * 16 + acol) * 2;
        ldsm4(qh[mt][0], qh[mt][1], qh[mt][2], qh[mt][3], qhB + off);
        ldsm4(ql[mt][0], ql[mt][1], ql[mt][2], ql[mt][3], qlB + off);
    }

    const uint32_t khB = s2u(sKh), klB = s2u(sKl);
    const uint32_t vhB = s2u(sVh), vlB = s2u(sVl);

    float mrow[2][2], lrow[2][2], acc[2][2][4];
    #pragma unroll
    for (int mt = 0; mt < 2; mt++)
        #pragma unroll
        for (int hf = 0; hf < 2; hf++) {
            mrow[mt][hf] = -1e30f; lrow[mt][hf] = 0.f;
            acc[mt][0][hf*2] = acc[mt][0][hf*2+1] = 0.f;
            acc[mt][1][hf*2] = acc[mt][1][hf*2+1] = 0.f;
        }

    for (int kt = 0; kt < 6; kt++) {
        __syncthreads();
        {
            int i = tid;
            int key = i >> 1, seg = (i & 1) * 2;     // seg in {0,2}
            int n = kt * 64 + key;
            const float* base = qkvT + (rowbase + (n < Nn ? n : 0)) * 384 + h * 16;
            float4 kv0 = make_float4(0,0,0,0), kv1 = make_float4(0,0,0,0);
            float4 vv0 = make_float4(0,0,0,0), vv1 = make_float4(0,0,0,0);
            if (n < Nn) {
                kv0 = ((const float4*)(base + 128))[seg];
                kv1 = ((const float4*)(base + 128))[seg + 1];
                vv0 = ((const float4*)(base + 256))[seg];
                vv1 = ((const float4*)(base + 256))[seg + 1];
            }
            uint32_t h0, l0, h1, l1;
            split2(kv0.x, kv0.y, h0, l0); split2(kv0.z, kv0.w, h1, l1);
            *(uint32_t*)&sKh[key * 16 + seg * 4]     = h0;
            *(uint32_t*)&sKh[key * 16 + seg * 4 + 2] = h1;
            *(uint32_t*)&sKl[key * 16 + seg * 4]     = l0;
            *(uint32_t*)&sKl[key * 16 + seg * 4 + 2] = l1;
            split2(kv1.x, kv1.y, h0, l0); split2(kv1.z, kv1.w, h1, l1);
            *(uint32_t*)&sKh[key * 16 + seg * 4 + 4] = h0;
            *(uint32_t*)&sKh[key * 16 + seg * 4 + 6] = h1;
            *(uint32_t*)&sKl[key * 16 + seg * 4 + 4] = l0;
            *(uint32_t*)&sKl[key * 16 + seg * 4 + 6] = l1;
            float vf[8] = {vv0.x, vv0.y, vv0.z, vv0.w, vv1.x, vv1.y, vv1.z, vv1.w};
            #pragma unroll
            for (int d = 0; d < 8; d++) {
                float x = vf[d];
                __nv_bfloat16 hb = __float2bfloat16(x);
                sVh[(seg * 4 + d) * 64 + key] = hb;
                sVl[(seg * 4 + d) * 64 + key] = __float2bfloat16(x - __bfloat162float(hb));
            }
        }
        __syncthreads();

        #pragma unroll
        for (int mt = 0; mt < 2; mt++) {
            float sc[8][4];
            #pragma unroll
            for (int nt = 0; nt < 8; nt++) { sc[nt][0]=sc[nt][1]=sc[nt][2]=sc[nt][3]=0.f; }
            #pragma unroll
            for (int np = 0; np < 4; np++) {
                uint32_t off = (uint32_t)((np * 16 + bnof) * 16 + bkof) * 2;
                uint32_t kh[2][2], kl[2][2];
                ldsm4(kh[0][0], kh[0][1], kh[1][0], kh[1][1], khB + off);
                ldsm4(kl[0][0], kl[0][1], kl[1][0], kl[1][1], klB + off);
                #pragma unroll
                for (int half = 0; half < 2; half++) {
                    int nt = np * 2 + half;
                    mma_bf16(sc[nt], qh[mt], kh[half]);
                    mma_bf16(sc[nt], qh[mt], kl[half]);
                    mma_bf16(sc[nt], ql[mt], kh[half]);
                }
            }
            #pragma unroll
            for (int nt = 0; nt < 8; nt++) {
                float2 mb = *(float2*)&mbias[kt * 64 + nt * 8 + (lane & 3) * 2];
                sc[nt][0] = sc[nt][0] * SCALE + mb.x;
                sc[nt][1] = sc[nt][1] * SCALE + mb.y;
                sc[nt][2] = sc[nt][2] * SCALE + mb.x;
                sc[nt][3] = sc[nt][3] * SCALE + mb.y;
            }
            float mx0 = -1e30f, mx1 = -1e30f;
            #pragma unroll
            for (int nt = 0; nt < 8; nt++) {
                mx0 = fmaxf(mx0, fmaxf(sc[nt][0], sc[nt][1]));
                mx1 = fmaxf(mx1, fmaxf(sc[nt][2], sc[nt][3]));
            }
            #pragma unroll
            for (int o = 1; o <= 2; o <<= 1) {
                mx0 = fmaxf(mx0, __shfl_xor_sync(0xffffffffu, mx0, o));
                mx1 = fmaxf(mx1, __shfl_xor_sync(0xffffffffu, mx1, o));
            }
            float mn0 = fmaxf(mrow[mt][0], mx0);
            float mn1 = fmaxf(mrow[mt][1], mx1);
            float cor0 = __expf(mrow[mt][0] - mn0);
            float cor1 = __expf(mrow[mt][1] - mn1);
            mrow[mt][0] = mn0; mrow[mt][1] = mn1;
            float ls0 = 0.f, ls1 = 0.f;
            uint32_t aph[4][4], apl[4][4];
            #pragma unroll
            for (int kk = 0; kk < 4; kk++) {
                #pragma unroll
                for (int half = 0; half < 2; half++) {
                    int nt = kk * 2 + half;
                    float p0 = (sc[nt][0] > -1e29f) ? __expf(sc[nt][0] - mn0) : 0.f;
                    float p1 = (sc[nt][1] > -1e29f) ? __expf(sc[nt][1] - mn0) : 0.f;
                    float p2 = (sc[nt][2] > -1e29f) ? __expf(sc[nt][2] - mn1) : 0.f;
                    float p3 = (sc[nt][3] > -1e29f) ? __expf(sc[nt][3] - mn1) : 0.f;
                    ls0 += p0 + p1; ls1 += p2 + p3;
                    uint32_t h01, l01, h23, l23;
                    split2(p0, p1, h01, l01);
                    split2(p2, p3, h23, l23);
                    aph[kk][half * 2 + 0] = h01;
                    aph[kk][half * 2 + 1] = h23;
                    apl[kk][half * 2 + 0] = l01;
                    apl[kk][half * 2 + 1] = l23;
                }
            }
            lrow[mt][0] = lrow[mt][0] * cor0 + ls0;
            lrow[mt][1] = lrow[mt][1] * cor1 + ls1;
            #pragma unroll
            for (int nv = 0; nv < 2; nv++) {
                acc[mt][nv][0] *= cor0; acc[mt][nv][1] *= cor0;
                acc[mt][nv][2] *= cor1; acc[mt][nv][3] *= cor1;
            }
            #pragma unroll
            for (int kk = 0; kk < 4; kk++) {
                uint32_t off = (uint32_t)(bnof * 64 + kk * 16 + bkof) * 2;
                uint32_t vh[2][2], vl[2][2];
                ldsm4(vh[0][0], vh[0][1], vh[1][0], vh[1][1], vhB + off);
                ldsm4(vl[0][0], vl[0][1], vl[1][0], vl[1][1], vlB + off);
                #pragma unroll
                for (int nv = 0; nv < 2; nv++) {
                    mma_bf16(acc[mt][nv], aph[kk], vh[nv]);
                    mma_bf16(acc[mt][nv], aph[kk], vl[nv]);
                    mma_bf16(acc[mt][nv], apl[kk], vh[nv]);
                }
            }
        }
    }

    #pragma unroll
    for (int mt = 0; mt < 2; mt++) {
        float l0 = lrow[mt][0], l1 = lrow[mt][1];
        #pragma unroll
        for (int o = 1; o <= 2; o <<= 1) {
            l0 += __shfl_xor_sync(0xffffffffu, l0, o);
            l1 += __shfl_xor_sync(0xffffffffu, l1, o);
        }
        float inv0 = 1.0f / l0, inv1 = 1.0f / l1;
        #pragma unroll
        for (int hf = 0; hf < 2; hf++) {
            int row = q0 + warp * 32 + mt * 16 + (lane >> 2) + hf * 8;
            if (row < Nn) {
                float inv = hf ? inv1 : inv0;
                size_t tok = ((size_t)(b * Nn + row)) * Tt + t;   // TOKEN order
                #pragma unroll
                for (int nv = 0; nv < 2; nv++) {
                    int d = nv * 8 + (lane & 3) * 2;
                    float o0 = acc[mt][nv][hf * 2 + 0] * inv;
                    float o1 = acc[mt][nv][hf * 2 + 1] * inv;
                    uint32_t hh, ll;
                    split2(o0, o1, hh, ll);
                    *(uint32_t*)&Ohi[tok * 128 + h * 16 + d] = hh;
                    *(uint32_t*)&Olo[tok * 128 + h * 16 + d] = ll;
                }
            }
        }
    }
}

// ---------------------------------------------------------------------------
// Orchestration
// ---------------------------------------------------------------------------
extern "C" void kernel_launch(void* const* d_in, const int* in_sizes, int n_in,
                              void* d_out, int out_size)
{
    const float* x       = (const float*)d_in[0];
    const int*   mask    = (const int*)  d_in[1];
    const float* ln1_s   = (const float*)d_in[2];
    const float* ln1_b   = (const float*)d_in[3];
    const float* tqkv_w  = (const float*)d_in[4];
    const float* tqkv_b  = (const float*)d_in[5];
    const float* tproj_w = (const float*)d_in[6];
    const float* tproj_b = (const float*)d_in[7];
    const float* ln2_s   = (const float*)d_in[8];
    const float* ln2_b   = (const float*)d_in[9];
    const float* sqkv_w  = (const float*)d_in[10];
    const float* sqkv_b  = (const float*)d_in[11];
    const float* sproj_w = (const float*)d_in[12];
    const float* sproj_b = (const float*)d_in[13];
    const float* ln3_s   = (const float*)d_in[14];
    const float* ln3_b   = (const float*)d_in[15];
    const float* fw1     = (const float*)d_in[16];
    const float* fb1     = (const float*)d_in[17];
    const float* fw2     = (const float*)d_in[18];
    const float* fb2     = (const float*)d_in[19];
    float* out = (float*)d_out;

    float *qkv, *x1, *x2;
    __nv_bfloat16 *hh, *hl, *ah, *al, *fh, *fl, *wh, *wl;
    cudaGetSymbolAddress((void**)&qkv, g_qkv);
    cudaGetSymbolAddress((void**)&x1,  g_x1);
    cudaGetSymbolAddress((void**)&x2,  g_x2);
    cudaGetSymbolAddress((void**)&hh,  g_hh);
    cudaGetSymbolAddress((void**)&hl,  g_hl);
    cudaGetSymbolAddress((void**)&ah,  g_ah);
    cudaGetSymbolAddress((void**)&al,  g_al);
    cudaGetSymbolAddress((void**)&fh,  g_fh);
    cudaGetSymbolAddress((void**)&fl,  g_fl);
    cudaGetSymbolAddress((void**)&wh,  g_wh);
    cudaGetSymbolAddress((void**)&wl,  g_wl);

    cudaFuncSetAttribute(gemm_bf<0>,    cudaFuncAttributeMaxDynamicSharedMemorySize, GSMEM);
    cudaFuncSetAttribute(gemm_bf<1>,    cudaFuncAttributeMaxDynamicSharedMemorySize, GSMEM);
    cudaFuncSetAttribute(gemm_bf<2>,    cudaFuncAttributeMaxDynamicSharedMemorySize, GSMEM);
    cudaFuncSetAttribute((const void*)gemm_bf<0,1>, cudaFuncAttributeMaxDynamicSharedMemorySize, GSMEM);

    // one-time weight transpose + split (single launch)
    wsplit_all<<<1024, 256>>>(tqkv_w, tproj_w, sqkv_w, sproj_w, fw1, fw2, wh, wl);

    const int ln_grid = (M + 7) / 8;
    dim3 g_qkv_grid(3, MT);    // N=384
    dim3 g_d_grid  (1, MT);    // N=128
    dim3 g_ffn1    (4, MT);    // N=512
    dim3 g_spat    (3, Hh, Bb * Tt);

    // ---- temporal branch ----
    ln_kernel<<<ln_grid, 256>>>(x, ln1_s, ln1_b, hh, hl, M);
    gemm_bf<0><<<g_qkv_grid, 256, GSMEM>>>(hh, hl, wh + W_TQKV, wl + W_TQKV,
                                           tqkv_b, nullptr, qkv, nullptr, nullptr, 384, 128, M);
    attn_temporal<<<Bb * Nn * Hh, 64>>>(qkv, ah, al);
    gemm_bf<1><<<g_d_grid, 256, GSMEM>>>(ah, al, wh + W_TPRJ, wl + W_TPRJ,
                                         tproj_b, x, x1, nullptr, nullptr, 128, 128, M);

    // ---- spatial branch: qkv written transposed; attn writes token order ----
    ln_kernel<<<ln_grid, 256>>>(x1, ln2_s, ln2_b, hh, hl, M);
    gemm_bf<0,1><<<g_qkv_grid, 256, GSMEM>>>(hh, hl, wh + W_SQKV, wl + W_SQKV,
                                             sqkv_b, nullptr, qkv, nullptr, nullptr, 384, 128, M);
    attn_spatial_mma<<<g_spat, 128>>>(qkv, mask, ah, al);
    gemm_bf<1><<<g_d_grid, 256, GSMEM>>>(ah, al, wh + W_SPRJ, wl + W_SPRJ,
                                         sproj_b, x1, x2, nullptr, nullptr, 128, 128, M);

    // ---- FFN ----
    ln_kernel<<<ln_grid, 256>>>(x2, ln3_s, ln3_b, hh, hl, M);
    gemm_bf<2><<<g_ffn1, 256, GSMEM>>>(hh, hl, wh + W_FW1, wl + W_FW1,
                                       fb1, nullptr, nullptr, fh, fl, 512, 128, M);
    gemm_bf<1><<<g_d_grid, 256, GSMEM>>>(fh, fl, wh + W_FW2, wl + W_FW2,
                                         fb2, x2, out, nullptr, nullptr, 128, 512, M);
}

// round 17
// speedup vs baseline: 1.9263x; 1.1227x over previous
#include <cuda_runtime.h>
#include <cuda_bf16.h>
#include <math.h>
#include <stdint.h>

// Problem constants
constexpr int Bb = 4, Nn = 325, Tt = 48, Hh = 8;
constexpr int M  = Bb * Nn * Tt;      // 62400 tokens
constexpr int MT = 488;               // M tiles of 128
constexpr int M_PAD = MT * 128;       // 62464
constexpr float SCALE = 0.25f;        // HD^-0.5, HD=16
constexpr float EPS = 1e-5f;

// Scratch (device globals, zero-initialized; pad rows [M, M_PAD) never written)
__device__ float g_qkv[M_PAD * 384];
__device__ float g_x1 [M_PAD * 128];
__device__ float g_x2 [M_PAD * 128];
__device__ __nv_bfloat16 g_hh[M_PAD * 128], g_hl[M_PAD * 128];   // LN out hi/lo
__device__ __nv_bfloat16 g_ah[M_PAD * 128], g_al[M_PAD * 128];   // attn out hi/lo
__device__ __nv_bfloat16 g_fh[M_PAD * 512], g_fl[M_PAD * 512];   // ffn1 out hi/lo
__device__ __nv_bfloat16 g_wh[262144],      g_wl[262144];        // weights^T hi/lo

// Weight segment offsets in g_wh/g_wl ([N,K] layout each)
constexpr int W_TQKV = 0;        // 384x128
constexpr int W_TPRJ = 49152;    // 128x128
constexpr int W_SQKV = 65536;    // 384x128
constexpr int W_SPRJ = 114688;   // 128x128
constexpr int W_FW1  = 131072;   // 512x128
constexpr int W_FW2  = 196608;   // 128x512

// ---------------------------------------------------------------------------
// Baseline-PTX helpers (sm_80-class: mma.sync, ldmatrix, cp.async)
// ---------------------------------------------------------------------------
__device__ __forceinline__ uint32_t s2u(const void* p) {
    uint32_t a;
    asm("{ .reg .u64 t; cvta.to.shared.u64 t, %1; cvt.u32.u64 %0, t; }"
        : "=r"(a) : "l"(p));
    return a;
}

__device__ __forceinline__ void ldsm4(uint32_t& r0, uint32_t& r1,
                                      uint32_t& r2, uint32_t& r3, uint32_t a) {
    asm volatile("ldmatrix.sync.aligned.m8n8.x4.shared.b16 {%0,%1,%2,%3}, [%4];"
                 : "=r"(r0), "=r"(r1), "=r"(r2), "=r"(r3) : "r"(a));
}

__device__ __forceinline__ void ldsm4t(uint32_t& r0, uint32_t& r1,
                                       uint32_t& r2, uint32_t& r3, uint32_t a) {
    asm volatile("ldmatrix.sync.aligned.m8n8.x4.trans.shared.b16 {%0,%1,%2,%3}, [%4];"
                 : "=r"(r0), "=r"(r1), "=r"(r2), "=r"(r3) : "r"(a));
}

__device__ __forceinline__ void mma_bf16(float* c, const uint32_t* a, const uint32_t* b) {
    asm volatile(
        "mma.sync.aligned.m16n8k16.row.col.f32.bf16.bf16.f32 "
        "{%0,%1,%2,%3}, {%4,%5,%6,%7}, {%8,%9}, {%0,%1,%2,%3};"
        : "+f"(c[0]), "+f"(c[1]), "+f"(c[2]), "+f"(c[3])
        : "r"(a[0]), "r"(a[1]), "r"(a[2]), "r"(a[3]), "r"(b[0]), "r"(b[1]));
}

__device__ __forceinline__ void cpasync16(uint32_t dst, const void* src) {
    asm volatile("cp.async.cg.shared.global [%0], [%1], 16;" :: "r"(dst), "l"(src));
}

// fp32 pair -> bf16 hi + bf16 lo (residual) packed as b32
__device__ __forceinline__ void split2(float x, float y, uint32_t& hi, uint32_t& lo) {
    __nv_bfloat162 h = __floats2bfloat162_rn(x, y);
    float rx = x - __bfloat162float(__low2bfloat16(h));
    float ry = y - __bfloat162float(__high2bfloat16(h));
    __nv_bfloat162 l = __floats2bfloat162_rn(rx, ry);
    hi = *(uint32_t*)&h;
    lo = *(uint32_t*)&l;
}

// token row (b,n,t) -> transposed row (b,t,n). Used only on epilogue WRITES.
__device__ __forceinline__ int tok2trans(int r) {
    int b = r / 15600, rr = r % 15600;
    int n = rr / 48, t = rr % 48;
    return b * 15600 + t * 325 + n;
}

// ---------------------------------------------------------------------------
// Fused weight transpose + split for all 6 weight matrices (one launch)
// ---------------------------------------------------------------------------
__global__ void wsplit_all(const float* __restrict__ w0, const float* __restrict__ w1,
                           const float* __restrict__ w2, const float* __restrict__ w3,
                           const float* __restrict__ w4, const float* __restrict__ w5,
                           __nv_bfloat16* __restrict__ hi, __nv_bfloat16* __restrict__ lo)
{
    int idx = blockIdx.x * 256 + threadIdx.x;
    if (idx >= 262144) return;
    const float* W; int K, N, local;
    if      (idx < 49152)  { W = w0; K = 128; N = 384; local = idx; }
    else if (idx < 65536)  { W = w1; K = 128; N = 128; local = idx - 49152; }
    else if (idx < 114688) { W = w2; K = 128; N = 384; local = idx - 65536; }
    else if (idx < 131072) { W = w3; K = 128; N = 128; local = idx - 114688; }
    else if (idx < 196608) { W = w4; K = 128; N = 512; local = idx - 131072; }
    else                   { W = w5; K = 512; N = 128; local = idx - 196608; }
    int n = local / K, k = local % K;
    float v = W[(size_t)k * N + n];
    __nv_bfloat16 h = __float2bfloat16(v);
    hi[idx] = h;
    lo[idx] = __float2bfloat16(v - __bfloat162float(h));
}

// ---------------------------------------------------------------------------
// LayerNorm: one warp per token row of 128 floats; outputs bf16 hi/lo
// ---------------------------------------------------------------------------
__global__ void ln_kernel(const float* __restrict__ X,
                          const float* __restrict__ s,
                          const float* __restrict__ b,
                          __nv_bfloat16* __restrict__ Ohi,
                          __nv_bfloat16* __restrict__ Olo, int rows)
{
    int gw   = (blockIdx.x * blockDim.x + threadIdx.x) >> 5;
    int lane = threadIdx.x & 31;
    if (gw >= rows) return;
    float4 v = ((const float4*)(X + (size_t)gw * 128))[lane];
    float sum = v.x + v.y + v.z + v.w;
    #pragma unroll
    for (int o = 16; o; o >>= 1) sum += __shfl_xor_sync(0xffffffffu, sum, o);
    float mean = sum * (1.0f / 128.0f);
    float dx = (v.x - mean) * (v.x - mean) + (v.y - mean) * (v.y - mean)
             + (v.z - mean) * (v.z - mean) + (v.w - mean) * (v.w - mean);
    #pragma unroll
    for (int o = 16; o; o >>= 1) dx += __shfl_xor_sync(0xffffffffu, dx, o);
    float rstd = rsqrtf(dx * (1.0f / 128.0f) + EPS);
    float4 sv = ((const float4*)s)[lane];
    float4 bv = ((const float4*)b)[lane];
    float o0 = (v.x - mean) * rstd * sv.x + bv.x;
    float o1 = (v.y - mean) * rstd * sv.y + bv.y;
    float o2 = (v.z - mean) * rstd * sv.z + bv.z;
    float o3 = (v.w - mean) * rstd * sv.w + bv.w;
    uint32_t h0, l0, h1, l1;
    split2(o0, o1, h0, l0);
    split2(o2, o3, h1, l1);
    uint2 hv; hv.x = h0; hv.y = h1;
    uint2 lv; lv.x = l0; lv.y = l1;
    ((uint2*)(Ohi + (size_t)gw * 128))[lane] = hv;
    ((uint2*)(Olo + (size_t)gw * 128))[lane] = lv;
}

// ---------------------------------------------------------------------------
// Pre-split bf16 tensor-core GEMM: C = Ahi/lo @ (Bhi/lo)^T + bias (+res)(gelu)
// CTA 128x128, BK=32, 256 threads; double-buffered cp.async; 2 CTAs/SM.
// EPI: 0 = bias->fp32 C; 1 = bias+res->fp32 C; 2 = bias+GELU->bf16 hi/lo C
// WPERM: 1 = epilogue writes C row tok2trans(r) (loads stay coalesced)
// ---------------------------------------------------------------------------
constexpr int ST = 40;                 // smem row stride in bf16 (80B)
constexpr int BUF = 128 * ST * 2;      // 10240 B per operand buffer
constexpr int STAGE = 4 * BUF;         // 40960 B per stage
constexpr int GSMEM = 2 * STAGE;       // 81920 B total

template <int EPI, int WPERM = 0>
__global__ __launch_bounds__(256, 2)
void gemm_bf(const __nv_bfloat16* __restrict__ Ahi, const __nv_bfloat16* __restrict__ Alo,
             const __nv_bfloat16* __restrict__ Bhi, const __nv_bfloat16* __restrict__ Blo,
             const float* __restrict__ bias, const float* __restrict__ Res,
             float* __restrict__ C,
             __nv_bfloat16* __restrict__ Chi, __nv_bfloat16* __restrict__ Clo,
             int Nc, int K, int Mreal)
{
    extern __shared__ char smem[];
    const int tid  = threadIdx.x;
    const int lane = tid & 31;
    const int wid  = tid >> 5;
    const int wm   = wid & 3;
    const int wn   = wid >> 2;
    const int m0   = blockIdx.y * 128;
    const int gn0  = blockIdx.x * 128;
    const uint32_t sbase = s2u(smem);

    float acc[2][8][4] = {};
    const int nch = K / 32;

    const int asub = lane >> 3;
    const int arow = (lane & 7) + (asub & 1) * 8;
    const int acol = (asub >> 1) * 8;
    const int bnof = (lane & 7) + ((lane >> 3) >> 1) * 8;
    const int bkof = ((lane >> 3) & 1) * 8;

    auto issue = [&](int c) {
        const int k0 = c * 32;
        const uint32_t st = sbase + (c & 1) * STAGE;
        #pragma unroll
        for (int i = 0; i < 2; i++) {
            int u = i * 256 + tid, row = u >> 2, g = u & 3;
            size_t go = (size_t)(m0 + row) * K + k0 + g * 8;
            uint32_t dst = st + row * 80 + g * 16;
            cpasync16(dst,       Ahi + go);
            cpasync16(dst + BUF, Alo + go);
        }
        #pragma unroll
        for (int i = 0; i < 2; i++) {
            int u = i * 256 + tid, n = u >> 2, g = u & 3;
            size_t go = (size_t)(gn0 + n) * K + k0 + g * 8;
            uint32_t dst = st + 2 * BUF + n * 80 + g * 16;
            cpasync16(dst,       Bhi + go);
            cpasync16(dst + BUF, Blo + go);
        }
        asm volatile("cp.async.commit_group;");
    };

    issue(0);
    for (int c = 0; c < nch; c++) {
        if (c + 1 < nch) {
            issue(c + 1);
            asm volatile("cp.async.wait_group 1;");
        } else {
            asm volatile("cp.async.wait_group 0;");
        }
        __syncthreads();

        const uint32_t aH = sbase + (c & 1) * STAGE;
        const uint32_t aL = aH + BUF;
        const uint32_t bH = aH + 2 * BUF;
        const uint32_t bL = aH + 3 * BUF;

        #pragma unroll
        for (int ks = 0; ks < 2; ks++) {
            uint32_t ah[2][4], al[2][4];
            #pragma unroll
            for (int mt = 0; mt < 2; mt++) {
                uint32_t off = (uint32_t)((wm * 32 + mt * 16 + arow) * ST + ks * 16 + acol) * 2;
                ldsm4(ah[mt][0], ah[mt][1], ah[mt][2], ah[mt][3], aH + off);
                ldsm4(al[mt][0], al[mt][1], al[mt][2], al[mt][3], aL + off);
            }
            #pragma unroll
            for (int np = 0; np < 4; np++) {
                uint32_t off = (uint32_t)((wn * 64 + np * 16 + bnof) * ST + ks * 16 + bkof) * 2;
                uint32_t bh[2][2], bl[2][2];
                ldsm4(bh[0][0], bh[0][1], bh[1][0], bh[1][1], bH + off);
                ldsm4(bl[0][0], bl[0][1], bl[1][0], bl[1][1], bL + off);
                #pragma unroll
                for (int half = 0; half < 2; half++) {
                    int nt = np * 2 + half;
                    #pragma unroll
                    for (int mt = 0; mt < 2; mt++) {
                        mma_bf16(acc[mt][nt], ah[mt], bh[half]);
                        mma_bf16(acc[mt][nt], ah[mt], bl[half]);
                        mma_bf16(acc[mt][nt], al[mt], bh[half]);
                    }
                }
            }
        }
        __syncthreads();
    }

    const int r0 = m0 + wm * 32 + (lane >> 2);
    const int c0 = gn0 + wn * 64 + (lane & 3) * 2;
    #pragma unroll
    for (int mt = 0; mt < 2; mt++) {
        #pragma unroll
        for (int half = 0; half < 2; half++) {
            int r = r0 + mt * 16 + half * 8;
            if (r < Mreal) {
                int wr = (WPERM == 1) ? tok2trans(r) : r;
                #pragma unroll
                for (int nt = 0; nt < 8; nt++) {
                    int cc = c0 + nt * 8;
                    float v0 = acc[mt][nt][half * 2 + 0] + bias[cc];
                    float v1 = acc[mt][nt][half * 2 + 1] + bias[cc + 1];
                    if (EPI == 1) {
                        float2 rv = *(const float2*)(Res + (size_t)r * Nc + cc);
                        v0 += rv.x; v1 += rv.y;
                    }
                    if (EPI == 2) {
                        v0 = 0.5f * v0 * (1.0f + erff(v0 * 0.70710678118654752f));
                        v1 = 0.5f * v1 * (1.0f + erff(v1 * 0.70710678118654752f));
                        uint32_t h, l;
                        split2(v0, v1, h, l);
                        *(uint32_t*)(Chi + (size_t)wr * Nc + cc) = h;
                        *(uint32_t*)(Clo + (size_t)wr * Nc + cc) = l;
                    } else {
                        float2 o; o.x = v0; o.y = v1;
                        *(float2*)(C + (size_t)wr * Nc + cc) = o;
                    }
                }
            }
        }
    }
}

// ---------------------------------------------------------------------------
// Temporal attention via mma.sync: block per (b,n), 128 threads, warp = 2 heads.
// One coalesced load of the 48x384 qkv slab -> split bf16 hi/lo smem
// (row stride 392 bf16 = 784B, odd multiple of 16B -> conflict-free ldmatrix).
// S = Q K^T (3-term split), exact single-pass softmax (48 keys resident),
// P normalized before PV; V fragments via ldmatrix.x4.trans on [key][dim].
// ---------------------------------------------------------------------------
constexpr int TST = 392;                        // bf16 row stride
constexpr int TSMEM = 2 * 48 * TST * 2;         // 75,264 B

__global__ __launch_bounds__(128)
void attn_temporal_mma(const float* __restrict__ qkv,
                       __nv_bfloat16* __restrict__ Ohi, __nv_bfloat16* __restrict__ Olo)
{
    extern __shared__ __nv_bfloat16 sm[];
    __nv_bfloat16* sH = sm;
    __nv_bfloat16* sL = sm + 48 * TST;

    const int tid = threadIdx.x, lane = tid & 31, warp = tid >> 5;
    const int bn = blockIdx.x;

    // coalesced load + split: 48 rows x 96 float4
    const float4* src = (const float4*)(qkv + (size_t)bn * 48 * 384);
    #pragma unroll 4
    for (int i = tid; i < 4608; i += 128) {
        int row = i / 96, c4 = i % 96;
        float4 v = src[i];
        uint32_t h0, l0, h1, l1;
        split2(v.x, v.y, h0, l0);
        split2(v.z, v.w, h1, l1);
        uint2 hv; hv.x = h0; hv.y = h1;
        uint2 lv; lv.x = l0; lv.y = l1;
        *(uint2*)&sH[row * TST + c4 * 4] = hv;
        *(uint2*)&sL[row * TST + c4 * 4] = lv;
    }
    __syncthreads();

    const int asub = lane >> 3;
    const int arow = (lane & 7) + (asub & 1) * 8;
    const int acol = (asub >> 1) * 8;
    const int bnof = (lane & 7) + ((lane >> 3) >> 1) * 8;
    const int bkof = ((lane >> 3) & 1) * 8;
    const int vrow = (lane & 7) + ((lane >> 3) & 1) * 8;   // key within 16
    const int vcol = (lane >> 4) * 8;                      // dim group

    const uint32_t sHb = s2u(sH), sLb = s2u(sL);

    #pragma unroll 1
    for (int hx = 0; hx < 2; hx++) {
        const int hh = warp * 2 + hx;
        const int qoff = hh * 16, koff = 128 + hh * 16, voff = 256 + hh * 16;

        // K fragments (6 n-tiles as 3 ldsm4 pairs) and V fragments (3 k-steps)
        uint32_t kh[3][4], kl[3][4], vh[3][4], vl[3][4];
        #pragma unroll
        for (int np = 0; np < 3; np++) {
            uint32_t off = (uint32_t)((np * 16 + bnof) * TST + koff + bkof) * 2;
            ldsm4(kh[np][0], kh[np][1], kh[np][2], kh[np][3], sHb + off);
            ldsm4(kl[np][0], kl[np][1], kl[np][2], kl[np][3], sLb + off);
        }
        #pragma unroll
        for (int kk = 0; kk < 3; kk++) {
            uint32_t off = (uint32_t)((kk * 16 + vrow) * TST + voff + vcol) * 2;
            ldsm4t(vh[kk][0], vh[kk][1], vh[kk][2], vh[kk][3], sHb + off);
            ldsm4t(vl[kk][0], vl[kk][1], vl[kk][2], vl[kk][3], sLb + off);
        }

        #pragma unroll 1
        for (int mt = 0; mt < 3; mt++) {
            uint32_t qh[4], ql[4];
            uint32_t qo = (uint32_t)((mt * 16 + arow) * TST + qoff + acol) * 2;
            ldsm4(qh[0], qh[1], qh[2], qh[3], sHb + qo);
            ldsm4(ql[0], ql[1], ql[2], ql[3], sLb + qo);

            float sc[6][4];
            #pragma unroll
            for (int nt = 0; nt < 6; nt++) { sc[nt][0]=sc[nt][1]=sc[nt][2]=sc[nt][3]=0.f; }
            #pragma unroll
            for (int np = 0; np < 3; np++)
                #pragma unroll
                for (int half = 0; half < 2; half++) {
                    int nt = np * 2 + half;
                    mma_bf16(sc[nt], qh, &kh[np][half * 2]);
                    mma_bf16(sc[nt], qh, &kl[np][half * 2]);
                    mma_bf16(sc[nt], ql, &kh[np][half * 2]);
                }

            // exact softmax (rows r and r+8, per quad)
            float mx0 = -3.4e38f, mx1 = -3.4e38f;
            #pragma unroll
            for (int nt = 0; nt < 6; nt++) {
                sc[nt][0] *= SCALE; sc[nt][1] *= SCALE;
                sc[nt][2] *= SCALE; sc[nt][3] *= SCALE;
                mx0 = fmaxf(mx0, fmaxf(sc[nt][0], sc[nt][1]));
                mx1 = fmaxf(mx1, fmaxf(sc[nt][2], sc[nt][3]));
            }
            #pragma unroll
            for (int o = 1; o <= 2; o <<= 1) {
                mx0 = fmaxf(mx0, __shfl_xor_sync(0xffffffffu, mx0, o));
                mx1 = fmaxf(mx1, __shfl_xor_sync(0xffffffffu, mx1, o));
            }
            float l0 = 0.f, l1 = 0.f;
            #pragma unroll
            for (int nt = 0; nt < 6; nt++) {
                sc[nt][0] = __expf(sc[nt][0] - mx0);
                sc[nt][1] = __expf(sc[nt][1] - mx0);
                sc[nt][2] = __expf(sc[nt][2] - mx1);
                sc[nt][3] = __expf(sc[nt][3] - mx1);
                l0 += sc[nt][0] + sc[nt][1];
                l1 += sc[nt][2] + sc[nt][3];
            }
            #pragma unroll
            for (int o = 1; o <= 2; o <<= 1) {
                l0 += __shfl_xor_sync(0xffffffffu, l0, o);
                l1 += __shfl_xor_sync(0xffffffffu, l1, o);
            }
            float inv0 = 1.0f / l0, inv1 = 1.0f / l1;

            // pack normalized P into A-fragments (k = 48 keys = 3 k-steps)
            uint32_t aph[3][4], apl[3][4];
            #pragma unroll
            for (int kk = 0; kk < 3; kk++)
                #pragma unroll
                for (int half = 0; half < 2; half++) {
                    int nt = kk * 2 + half;
                    float p0 = sc[nt][0] * inv0, p1 = sc[nt][1] * inv0;
                    float p2 = sc[nt][2] * inv1, p3 = sc[nt][3] * inv1;
                    uint32_t h01, l01, h23, l23;
                    split2(p0, p1, h01, l01);
                    split2(p2, p3, h23, l23);
                    aph[kk][half * 2 + 0] = h01;
                    aph[kk][half * 2 + 1] = h23;
                    apl[kk][half * 2 + 0] = l01;
                    apl[kk][half * 2 + 1] = l23;
                }

            // O = P V (3-term)
            float acc[2][4] = {};
            #pragma unroll
            for (int kk = 0; kk < 3; kk++)
                #pragma unroll
                for (int nv = 0; nv < 2; nv++) {
                    mma_bf16(acc[nv], aph[kk], &vh[kk][nv * 2]);
                    mma_bf16(acc[nv], aph[kk], &vl[kk][nv * 2]);
                    mma_bf16(acc[nv], apl[kk], &vh[kk][nv * 2]);
                }

            // store split-bf16 (P already normalized)
            #pragma unroll
            for (int hf = 0; hf < 2; hf++) {
                int row = mt * 16 + (lane >> 2) + hf * 8;
                size_t tok = (size_t)(bn * 48 + row);
                #pragma unroll
                for (int nv = 0; nv < 2; nv++) {
                    int d = hh * 16 + nv * 8 + (lane & 3) * 2;
                    uint32_t h, l;
                    split2(acc[nv][hf * 2 + 0], acc[nv][hf * 2 + 1], h, l);
                    *(uint32_t*)&Ohi[tok * 128 + d] = h;
                    *(uint32_t*)&Olo[tok * 128 + d] = l;
                }
            }
        }
    }
}

// ---------------------------------------------------------------------------
// Spatial attention via mma.sync on TRANSPOSED qkv (rows in (b,t,n) order,
// contiguous K/V tiles). Output written back in TOKEN order.
// ---------------------------------------------------------------------------
__global__ __launch_bounds__(128)
void attn_spatial_mma(const float* __restrict__ qkvT, const int* __restrict__ mask,
                      __nv_bfloat16* __restrict__ Ohi, __nv_bfloat16* __restrict__ Olo)
{
    __shared__ __nv_bfloat16 sQh[128 * 16], sQl[128 * 16];
    __shared__ __nv_bfloat16 sKh[64 * 16],  sKl[64 * 16];
    __shared__ __nv_bfloat16 sVh[16 * 64],  sVl[16 * 64];
    __shared__ float mbias[384];

    const int tid = threadIdx.x, lane = tid & 31, warp = tid >> 5;
    const int qt = blockIdx.x, h = blockIdx.y, z = blockIdx.z;  // z = b*48+t
    const int b = z / Tt, t = z % Tt;
    const int q0 = qt * 128;
    const size_t rowbase = (size_t)z * Nn;

    for (int j = tid; j < 384; j += 128)
        mbias[j] = (j < Nn && mask[b * Nn + j] != 0) ? 0.f : -1e30f;

    for (int i = tid; i < 512; i += 128) {
        int row = i >> 2, seg = i & 3;
        int n = q0 + row;
        float4 v = make_float4(0.f, 0.f, 0.f, 0.f);
        if (n < Nn)
            v = *(const float4*)(qkvT + (rowbase + n) * 384 + h * 16 + seg * 4);
        uint32_t h0, l0, h1, l1;
        split2(v.x, v.y, h0, l0);
        split2(v.z, v.w, h1, l1);
        *(uint32_t*)&sQh[row * 16 + seg * 4]     = h0;
        *(uint32_t*)&sQh[row * 16 + seg * 4 + 2] = h1;
        *(uint32_t*)&sQl[row * 16 + seg * 4]     = l0;
        *(uint32_t*)&sQl[row * 16 + seg * 4 + 2] = l1;
    }
    __syncthreads();

    const int asub = lane >> 3;
    const int arow = (lane & 7) + (asub & 1) * 8;
    const int acol = (asub >> 1) * 8;
    const int bnof = (lane & 7) + ((lane >> 3) >> 1) * 8;
    const int bkof = ((lane >> 3) & 1) * 8;

    uint32_t qh[2][4], ql[2][4];
    const uint32_t qhB = s2u(sQh), qlB = s2u(sQl);
    #pragma unroll
    for (int mt = 0; mt < 2; mt++) {
        uint32_t off = (uint32_t)((warp * 32 + mt * 16 + arow) * 16 + acol) * 2;
        ldsm4(qh[mt][0], qh[mt][1], qh[mt][2], qh[mt][3], qhB + off);
        ldsm4(ql[mt][0], ql[mt][1], ql[mt][2], ql[mt][3], qlB + off);
    }

    const uint32_t khB = s2u(sKh), klB = s2u(sKl);
    const uint32_t vhB = s2u(sVh), vlB = s2u(sVl);

    float mrow[2][2], lrow[2][2], acc[2][2][4];
    #pragma unroll
    for (int mt = 0; mt < 2; mt++)
        #pragma unroll
        for (int hf = 0; hf < 2; hf++) {
            mrow[mt][hf] = -1e30f; lrow[mt][hf] = 0.f;
            acc[mt][0][hf*2] = acc[mt][0][hf*2+1] = 0.f;
            acc[mt][1][hf*2] = acc[mt][1][hf*2+1] = 0.f;
        }

    for (int kt = 0; kt < 6; kt++) {
        __syncthreads();
        {
            int i = tid;
            int key = i >> 1, seg = (i & 1) * 2;     // seg in {0,2}
            int n = kt * 64 + key;
            const float* base = qkvT + (rowbase + (n < Nn ? n : 0)) * 384 + h * 16;
            float4 kv0 = make_float4(0,0,0,0), kv1 = make_float4(0,0,0,0);
            float4 vv0 = make_float4(0,0,0,0), vv1 = make_float4(0,0,0,0);
            if (n < Nn) {
                kv0 = ((const float4*)(base + 128))[seg];
                kv1 = ((const float4*)(base + 128))[seg + 1];
                vv0 = ((const float4*)(base + 256))[seg];
                vv1 = ((const float4*)(base + 256))[seg + 1];
            }
            uint32_t h0, l0, h1, l1;
            split2(kv0.x, kv0.y, h0, l0); split2(kv0.z, kv0.w, h1, l1);
            *(uint32_t*)&sKh[key * 16 + seg * 4]     = h0;
            *(uint32_t*)&sKh[key * 16 + seg * 4 + 2] = h1;
            *(uint32_t*)&sKl[key * 16 + seg * 4]     = l0;
            *(uint32_t*)&sKl[key * 16 + seg * 4 + 2] = l1;
            split2(kv1.x, kv1.y, h0, l0); split2(kv1.z, kv1.w, h1, l1);
            *(uint32_t*)&sKh[key * 16 + seg * 4 + 4] = h0;
            *(uint32_t*)&sKh[key * 16 + seg * 4 + 6] = h1;
            *(uint32_t*)&sKl[key * 16 + seg * 4 + 4] = l0;
            *(uint32_t*)&sKl[key * 16 + seg * 4 + 6] = l1;
            float vf[8] = {vv0.x, vv0.y, vv0.z, vv0.w, vv1.x, vv1.y, vv1.z, vv1.w};
            #pragma unroll
            for (int d = 0; d < 8; d++) {
                float x = vf[d];
                __nv_bfloat16 hb = __float2bfloat16(x);
                sVh[(seg * 4 + d) * 64 + key] = hb;
                sVl[(seg * 4 + d) * 64 + key] = __float2bfloat16(x - __bfloat162float(hb));
            }
        }
        __syncthreads();

        #pragma unroll
        for (int mt = 0; mt < 2; mt++) {
            float sc[8][4];
            #pragma unroll
            for (int nt = 0; nt < 8; nt++) { sc[nt][0]=sc[nt][1]=sc[nt][2]=sc[nt][3]=0.f; }
            #pragma unroll
            for (int np = 0; np < 4; np++) {
                uint32_t off = (uint32_t)((np * 16 + bnof) * 16 + bkof) * 2;
                uint32_t kh[2][2], kl[2][2];
                ldsm4(kh[0][0], kh[0][1], kh[1][0], kh[1][1], khB + off);
                ldsm4(kl[0][0], kl[0][1], kl[1][0], kl[1][1], klB + off);
                #pragma unroll
                for (int half = 0; half < 2; half++) {
                    int nt = np * 2 + half;
                    mma_bf16(sc[nt], qh[mt], kh[half]);
                    mma_bf16(sc[nt], qh[mt], kl[half]);
                    mma_bf16(sc[nt], ql[mt], kh[half]);
                }
            }
            #pragma unroll
            for (int nt = 0; nt < 8; nt++) {
                float2 mb = *(float2*)&mbias[kt * 64 + nt * 8 + (lane & 3) * 2];
                sc[nt][0] = sc[nt][0] * SCALE + mb.x;
                sc[nt][1] = sc[nt][1] * SCALE + mb.y;
                sc[nt][2] = sc[nt][2] * SCALE + mb.x;
                sc[nt][3] = sc[nt][3] * SCALE + mb.y;
            }
            float mx0 = -1e30f, mx1 = -1e30f;
            #pragma unroll
            for (int nt = 0; nt < 8; nt++) {
                mx0 = fmaxf(mx0, fmaxf(sc[nt][0], sc[nt][1]));
                mx1 = fmaxf(mx1, fmaxf(sc[nt][2], sc[nt][3]));
            }
            #pragma unroll
            for (int o = 1; o <= 2; o <<= 1) {
                mx0 = fmaxf(mx0, __shfl_xor_sync(0xffffffffu, mx0, o));
                mx1 = fmaxf(mx1, __shfl_xor_sync(0xffffffffu, mx1, o));
            }
            float mn0 = fmaxf(mrow[mt][0], mx0);
            float mn1 = fmaxf(mrow[mt][1], mx1);
            float cor0 = __expf(mrow[mt][0] - mn0);
            float cor1 = __expf(mrow[mt][1] - mn1);
            mrow[mt][0] = mn0; mrow[mt][1] = mn1;
            float ls0 = 0.f, ls1 = 0.f;
            uint32_t aph[4][4], apl[4][4];
            #pragma unroll
            for (int kk = 0; kk < 4; kk++) {
                #pragma unroll
                for (int half = 0; half < 2; half++) {
                    int nt = kk * 2 + half;
                    float p0 = (sc[nt][0] > -1e29f) ? __expf(sc[nt][0] - mn0) : 0.f;
                    float p1 = (sc[nt][1] > -1e29f) ? __expf(sc[nt][1] - mn0) : 0.f;
                    float p2 = (sc[nt][2] > -1e29f) ? __expf(sc[nt][2] - mn1) : 0.f;
                    float p3 = (sc[nt][3] > -1e29f) ? __expf(sc[nt][3] - mn1) : 0.f;
                    ls0 += p0 + p1; ls1 += p2 + p3;
                    uint32_t h01, l01, h23, l23;
                    split2(p0, p1, h01, l01);
                    split2(p2, p3, h23, l23);
                    aph[kk][half * 2 + 0] = h01;
                    aph[kk][half * 2 + 1] = h23;
                    apl[kk][half * 2 + 0] = l01;
                    apl[kk][half * 2 + 1] = l23;
                }
            }
            lrow[mt][0] = lrow[mt][0] * cor0 + ls0;
            lrow[mt][1] = lrow[mt][1] * cor1 + ls1;
            #pragma unroll
            for (int nv = 0; nv < 2; nv++) {
                acc[mt][nv][0] *= cor0; acc[mt][nv][1] *= cor0;
                acc[mt][nv][2] *= cor1; acc[mt][nv][3] *= cor1;
            }
            #pragma unroll
            for (int kk = 0; kk < 4; kk++) {
                uint32_t off = (uint32_t)(bnof * 64 + kk * 16 + bkof) * 2;
                uint32_t vh[2][2], vl[2][2];
                ldsm4(vh[0][0], vh[0][1], vh[1][0], vh[1][1], vhB + off);
                ldsm4(vl[0][0], vl[0][1], vl[1][0], vl[1][1], vlB + off);
                #pragma unroll
                for (int nv = 0; nv < 2; nv++) {
                    mma_bf16(acc[mt][nv], aph[kk], vh[nv]);
                    mma_bf16(acc[mt][nv], aph[kk], vl[nv]);
                    mma_bf16(acc[mt][nv], apl[kk], vh[nv]);
                }
            }
        }
    }

    #pragma unroll
    for (int mt = 0; mt < 2; mt++) {
        float l0 = lrow[mt][0], l1 = lrow[mt][1];
        #pragma unroll
        for (int o = 1; o <= 2; o <<= 1) {
            l0 += __shfl_xor_sync(0xffffffffu, l0, o);
            l1 += __shfl_xor_sync(0xffffffffu, l1, o);
        }
        float inv0 = 1.0f / l0, inv1 = 1.0f / l1;
        #pragma unroll
        for (int hf = 0; hf < 2; hf++) {
            int row = q0 + warp * 32 + mt * 16 + (lane >> 2) + hf * 8;
            if (row < Nn) {
                float inv = hf ? inv1 : inv0;
                size_t tok = ((size_t)(b * Nn + row)) * Tt + t;   // TOKEN order
                #pragma unroll
                for (int nv = 0; nv < 2; nv++) {
                    int d = nv * 8 + (lane & 3) * 2;
                    float o0 = acc[mt][nv][hf * 2 + 0] * inv;
                    float o1 = acc[mt][nv][hf * 2 + 1] * inv;
                    uint32_t hh, ll;
                    split2(o0, o1, hh, ll);
                    *(uint32_t*)&Ohi[tok * 128 + h * 16 + d] = hh;
                    *(uint32_t*)&Olo[tok * 128 + h * 16 + d] = ll;
                }
            }
        }
    }
}

// ---------------------------------------------------------------------------
// Orchestration
// ---------------------------------------------------------------------------
extern "C" void kernel_launch(void* const* d_in, const int* in_sizes, int n_in,
                              void* d_out, int out_size)
{
    const float* x       = (const float*)d_in[0];
    const int*   mask    = (const int*)  d_in[1];
    const float* ln1_s   = (const float*)d_in[2];
    const float* ln1_b   = (const float*)d_in[3];
    const float* tqkv_w  = (const float*)d_in[4];
    const float* tqkv_b  = (const float*)d_in[5];
    const float* tproj_w = (const float*)d_in[6];
    const float* tproj_b = (const float*)d_in[7];
    const float* ln2_s   = (const float*)d_in[8];
    const float* ln2_b   = (const float*)d_in[9];
    const float* sqkv_w  = (const float*)d_in[10];
    const float* sqkv_b  = (const float*)d_in[11];
    const float* sproj_w = (const float*)d_in[12];
    const float* sproj_b = (const float*)d_in[13];
    const float* ln3_s   = (const float*)d_in[14];
    const float* ln3_b   = (const float*)d_in[15];
    const float* fw1     = (const float*)d_in[16];
    const float* fb1     = (const float*)d_in[17];
    const float* fw2     = (const float*)d_in[18];
    const float* fb2     = (const float*)d_in[19];
    float* out = (float*)d_out;

    float *qkv, *x1, *x2;
    __nv_bfloat16 *hh, *hl, *ah, *al, *fh, *fl, *wh, *wl;
    cudaGetSymbolAddress((void**)&qkv, g_qkv);
    cudaGetSymbolAddress((void**)&x1,  g_x1);
    cudaGetSymbolAddress((void**)&x2,  g_x2);
    cudaGetSymbolAddress((void**)&hh,  g_hh);
    cudaGetSymbolAddress((void**)&hl,  g_hl);
    cudaGetSymbolAddress((void**)&ah,  g_ah);
    cudaGetSymbolAddress((void**)&al,  g_al);
    cudaGetSymbolAddress((void**)&fh,  g_fh);
    cudaGetSymbolAddress((void**)&fl,  g_fl);
    cudaGetSymbolAddress((void**)&wh,  g_wh);
    cudaGetSymbolAddress((void**)&wl,  g_wl);

    cudaFuncSetAttribute(gemm_bf<0>,    cudaFuncAttributeMaxDynamicSharedMemorySize, GSMEM);
    cudaFuncSetAttribute(gemm_bf<1>,    cudaFuncAttributeMaxDynamicSharedMemorySize, GSMEM);
    cudaFuncSetAttribute(gemm_bf<2>,    cudaFuncAttributeMaxDynamicSharedMemorySize, GSMEM);
    cudaFuncSetAttribute((const void*)gemm_bf<0,1>, cudaFuncAttributeMaxDynamicSharedMemorySize, GSMEM);
    cudaFuncSetAttribute(attn_temporal_mma, cudaFuncAttributeMaxDynamicSharedMemorySize, TSMEM);

    // one-time weight transpose + split (single launch)
    wsplit_all<<<1024, 256>>>(tqkv_w, tproj_w, sqkv_w, sproj_w, fw1, fw2, wh, wl);

    const int ln_grid = (M + 7) / 8;
    dim3 g_qkv_grid(3, MT);    // N=384
    dim3 g_d_grid  (1, MT);    // N=128
    dim3 g_ffn1    (4, MT);    // N=512
    dim3 g_spat    (3, Hh, Bb * Tt);

    // ---- temporal branch ----
    ln_kernel<<<ln_grid, 256>>>(x, ln1_s, ln1_b, hh, hl, M);
    gemm_bf<0><<<g_qkv_grid, 256, GSMEM>>>(hh, hl, wh + W_TQKV, wl + W_TQKV,
                                           tqkv_b, nullptr, qkv, nullptr, nullptr, 384, 128, M);
    attn_temporal_mma<<<Bb * Nn, 128, TSMEM>>>(qkv, ah, al);
    gemm_bf<1><<<g_d_grid, 256, GSMEM>>>(ah, al, wh + W_TPRJ, wl + W_TPRJ,
                                         tproj_b, x, x1, nullptr, nullptr, 128, 128, M);

    // ---- spatial branch: qkv written transposed; attn writes token order ----
    ln_kernel<<<ln_grid, 256>>>(x1, ln2_s, ln2_b, hh, hl, M);
    gemm_bf<0,1><<<g_qkv_grid, 256, GSMEM>>>(hh, hl, wh + W_SQKV, wl + W_SQKV,
                                             sqkv_b, nullptr, qkv, nullptr, nullptr, 384, 128, M);
    attn_spatial_mma<<<g_spat, 128>>>(qkv, mask, ah, al);
    gemm_bf<1><<<g_d_grid, 256, GSMEM>>>(ah, al, wh + W_SPRJ, wl + W_SPRJ,
                                         sproj_b, x1, x2, nullptr, nullptr, 128, 128, M);

    // ---- FFN ----
    ln_kernel<<<ln_grid, 256>>>(x2, ln3_s, ln3_b, hh, hl, M);
    gemm_bf<2><<<g_ffn1, 256, GSMEM>>>(hh, hl, wh + W_FW1, wl + W_FW1,
                                       fb1, nullptr, nullptr, fh, fl, 512, 128, M);
    gemm_bf<1><<<g_d_grid, 256, GSMEM>>>(fh, fl, wh + W_FW2, wl + W_FW2,
                                         fb2, x2, out, nullptr, nullptr, 128, 512, M);
}